// round 14
// baseline (speedup 1.0000x reference)
#include <cuda_runtime.h>
#include <cstdint>
#include <cstddef>

#define BATCH 4
#define NPTS  2048
#define ROWS  (BATCH*NPTS)   // 8192
#define CIN   128
#define COUT  256
#define K_NN  32

#define FINF __int_as_float(0x7f800000)
typedef unsigned long long ull;

// ---------------- scratch ----------------
__device__ float g_norms[ROWS];
__device__ float g_dist[(size_t)BATCH*NPTS*NPTS];          // 64 MB, write-once/read-once
__device__ int   g_idx0[ROWS*K_NN];
__device__ int   g_idx1[ROWS*K_NN];
__device__ float g_proj[(size_t)8*ROWS*COUT];              // q0,k0,v0,r0,q1,k1,v1,r1
__device__ float g_ctx[(size_t)2*ROWS*COUT];
__device__ float g_ffnh[(size_t)2*ROWS*COUT];
__device__ float g_mergeh[(size_t)ROWS*COUT];
__device__ float g_part[5*64*2*COUT];
__device__ float g_coef[5*COUT*2];

__device__ __forceinline__ float lrelu(float x){ return x > 0.f ? x : 0.2f*x; }

__device__ __forceinline__ uint32_t fkey(float f){
    uint32_t b = __float_as_uint(f);
    return b ^ (uint32_t)(((int)b >> 31) | 0x80000000);
}

// mask-based tf32 split (validated R7): hi = tf32 truncation, lo = exact residual.
__device__ __forceinline__ void tf32_split(float x, uint32_t& hi, uint32_t& lo){
    hi = __float_as_uint(x) & 0xFFFFE000u;
    lo = __float_as_uint(x - __uint_as_float(hi));
}

// ---------------- row squared norms of feature (one warp per row) ----------------
__global__ void norms_k(const float* __restrict__ feat){
    int w = (blockIdx.x*blockDim.x + threadIdx.x) >> 5;
    int lane = threadIdx.x & 31;
    if (w >= ROWS) return;
    float4 f4 = ((const float4*)(feat + (size_t)w*CIN))[lane];
    float s = f4.x*f4.x + f4.y*f4.y + f4.z*f4.z + f4.w*f4.w;
    #pragma unroll
    for (int o=16;o;o>>=1) s += __shfl_xor_sync(0xffffffffu, s, o);
    if (!lane) g_norms[w] = s;
}

// ---------------- register-key radix select (validated R10) ----------------
__device__ void select32_reg(const ull* __restrict__ k64, int* __restrict__ out){
    __shared__ int h[256];
    __shared__ int sc[256];
    __shared__ ull s_prefix, s_bound;
    __shared__ int s_need, s_done, s_cnt;
    int tid = threadIdx.x;
    if (tid == 0){ s_prefix = 0; s_need = K_NN; s_done = 0; s_cnt = 0; }
    int shift = 40;
    __syncthreads();
    while (true){
        h[tid] = 0;
        __syncthreads();
        ull pref = s_prefix;
        int need = s_need;
        #pragma unroll
        for (int i = 0; i < 8; i++){
            if ((k64[i] >> (shift + 8)) == pref)
                atomicAdd(&h[(int)((k64[i] >> shift) & 0xFF)], 1);
        }
        __syncthreads();
        int hv = h[tid];
        sc[tid] = hv;
        __syncthreads();
        #pragma unroll
        for (int o = 1; o < 256; o <<= 1){
            int u = (tid >= o) ? sc[tid - o] : 0;
            __syncthreads();
            sc[tid] += u;
            __syncthreads();
        }
        int incl = sc[tid], excl = incl - hv;
        if (excl < need && incl >= need){
            int nn = need - excl;
            if (hv == nn){
                s_bound = ((((pref << 8) | (ull)tid) + 1ull) << shift);
                s_done = 1;
            } else {
                s_prefix = (pref << 8) | (ull)tid;
                s_need = nn;
            }
        }
        __syncthreads();
        if (s_done) break;
        shift -= 8;
    }
    ull bound = s_bound;
    #pragma unroll
    for (int i = 0; i < 8; i++){
        if (k64[i] < bound){
            int p = atomicAdd(&s_cnt, 1);
            out[p] = (int)(k64[i] & 0xFFFFull);
        }
    }
}

// ---------------- xyz KNN: fused distance + reg-key selection ----------------
__global__ void knn_xyz_k(const float* __restrict__ xyz, const float* __restrict__ bxyz){
    __shared__ float sp[NPTS*3];
    int row = blockIdx.x;
    int b = row / NPTS;
    int tid = threadIdx.x;
    const float* bp = bxyz + (size_t)b*NPTS*3;
    for (int i = tid; i < NPTS*3; i += 256) sp[i] = bp[i];
    float qx = xyz[(size_t)row*3+0], qy = xyz[(size_t)row*3+1], qz = xyz[(size_t)row*3+2];
    float qn = qx*qx + qy*qy + qz*qz;
    __syncthreads();
    ull k64[8];
    #pragma unroll
    for (int i = 0; i < 8; i++){
        int m = tid + i*256;
        float px = sp[m*3+0], py = sp[m*3+1], pz = sp[m*3+2];
        float pn = px*px + py*py + pz*pz;
        float d = qn + pn - 2.f*(qx*px + qy*py + qz*pz);
        k64[i] = ((ull)fkey(d) << 16) | (ull)m;
    }
    select32_reg(k64, g_idx0 + (size_t)row*K_NN);
}

// ---------------- feature KNN selection (evict-first loads of dead dist data) --------
__global__ void select_feat_k(){
    int row = blockIdx.x;
    int tid = threadIdx.x;
    const float4* dr = (const float4*)(g_dist + (size_t)row*NPTS);
    ull k64[8];
    #pragma unroll
    for (int i = 0; i < 2; i++){
        float4 d4 = __ldcs(dr + i*256 + tid);
        int m = (i*256 + tid)*4;
        k64[i*4+0] = ((ull)fkey(d4.x) << 16) | (ull)(m+0);
        k64[i*4+1] = ((ull)fkey(d4.y) << 16) | (ull)(m+1);
        k64[i*4+2] = ((ull)fkey(d4.z) << 16) | (ull)(m+2);
        k64[i*4+3] = ((ull)fkey(d4.w) << 16) | (ull)(m+3);
    }
    select32_reg(k64, g_idx1 + (size_t)row*K_NN);
}

// ---------------- feature pairwise distance GEMM (fp32 SIMT — REQUIRED precision) ------
// 128x128 tile, 8x8 accum, conflict-free B mapping (tx + 16*j), float4 A-fragment LDS,
// streaming stores (dist is dead after select). Bitwise-identical distances to R13.
__global__ void __launch_bounds__(256) dist_gemm_k(const float* __restrict__ feat){
    int bz = blockIdx.z;
    const float* A = feat + (size_t)bz*NPTS*CIN;
    __shared__ float As[16][136];
    __shared__ float Bs[16][136];
    int tid = threadIdx.x, tx = tid & 15, ty = tid >> 4;
    int row0 = blockIdx.y*128, col0 = blockIdx.x*128;
    float acc[8][8] = {};
    int ar = tid >> 1, ac = (tid & 1) * 8;
    for (int k0 = 0; k0 < CIN; k0 += 16){
        float4 a4 = *(const float4*)(A + (size_t)(row0+ar)*CIN + k0 + ac);
        float4 a5 = *(const float4*)(A + (size_t)(row0+ar)*CIN + k0 + ac + 4);
        As[ac+0][ar]=a4.x; As[ac+1][ar]=a4.y; As[ac+2][ar]=a4.z; As[ac+3][ar]=a4.w;
        As[ac+4][ar]=a5.x; As[ac+5][ar]=a5.y; As[ac+6][ar]=a5.z; As[ac+7][ar]=a5.w;
        float4 b4 = *(const float4*)(A + (size_t)(col0+ar)*CIN + k0 + ac);
        float4 b5 = *(const float4*)(A + (size_t)(col0+ar)*CIN + k0 + ac + 4);
        Bs[ac+0][ar]=b4.x; Bs[ac+1][ar]=b4.y; Bs[ac+2][ar]=b4.z; Bs[ac+3][ar]=b4.w;
        Bs[ac+4][ar]=b5.x; Bs[ac+5][ar]=b5.y; Bs[ac+6][ar]=b5.z; Bs[ac+7][ar]=b5.w;
        __syncthreads();
        #pragma unroll
        for (int kk = 0; kk < 16; kk++){
            float av[8], bv[8];
            *(float4*)&av[0] = *(const float4*)&As[kk][ty*8];
            *(float4*)&av[4] = *(const float4*)&As[kk][ty*8+4];
            #pragma unroll
            for (int j=0;j<8;j++) bv[j] = Bs[kk][tx + 16*j];
            #pragma unroll
            for (int i=0;i<8;i++)
                #pragma unroll
                for (int j=0;j<8;j++) acc[i][j] += av[i]*bv[j];
        }
        __syncthreads();
    }
    float* D = g_dist + (size_t)bz*NPTS*NPTS;
    const float* qn = g_norms + bz*NPTS;
    #pragma unroll
    for (int i=0;i<8;i++){
        int n = row0 + ty*8 + i;
        float qnn = qn[n];
        #pragma unroll
        for (int j=0;j<8;j++){
            int m = col0 + tx + 16*j;
            __stcs(&D[(size_t)n*NPTS + m], qnn + qn[m] - 2.f*acc[i][j]);
        }
    }
}

// ================= 3xTF32 tensor-core GEMM (validated R7) =================
#define BM 128
#define BN 64
#define BKT 32
#define SM_WORDS (128*36*2 + 32*72*2)

struct GemmB { const float* A; const float* W; const float* bias; float* C; };
struct GemmP { GemmB b[8]; int K; };

__device__ __forceinline__ void mma_tf32(float* d, const uint32_t* a, const uint32_t* b){
    asm volatile(
        "mma.sync.aligned.m16n8k8.row.col.f32.tf32.tf32.f32 "
        "{%0,%1,%2,%3}, {%4,%5,%6,%7}, {%8,%9}, {%0,%1,%2,%3};\n"
        : "+f"(d[0]), "+f"(d[1]), "+f"(d[2]), "+f"(d[3])
        : "r"(a[0]), "r"(a[1]), "r"(a[2]), "r"(a[3]), "r"(b[0]), "r"(b[1]));
}

__global__ void __launch_bounds__(256) gemm3_k(GemmP p){
    __shared__ uint32_t sm[SM_WORDS];
    uint32_t (*Ah)[36] = (uint32_t(*)[36])sm;
    uint32_t (*Al)[36] = (uint32_t(*)[36])(sm + 128*36);
    uint32_t (*Bh)[72] = (uint32_t(*)[72])(sm + 128*36*2);
    uint32_t (*Bl)[72] = (uint32_t(*)[72])(sm + 128*36*2 + 32*72);

    int z = blockIdx.z;
    const float* A = p.b[z].A;
    const float* W = p.b[z].W;
    const float* bias = p.b[z].bias;
    float* C = p.b[z].C;
    int K = p.K;

    int tid = threadIdx.x, lane = tid & 31, wid = tid >> 5;
    int wm = (wid & 3) * 32, wn = (wid >> 2) * 32;
    int row0 = blockIdx.y*BM, col0 = blockIdx.x*BN;
    int g = lane >> 2, t = lane & 3;

    float acc[8][4];
    #pragma unroll
    for (int i=0;i<8;i++){ acc[i][0]=0.f; acc[i][1]=0.f; acc[i][2]=0.f; acc[i][3]=0.f; }

    int ar = tid >> 1, ac = (tid & 1) * 16;
    int br = tid >> 3, bc = (tid & 7) * 8;

    for (int k0 = 0; k0 < K; k0 += BKT){
        #pragma unroll
        for (int i = 0; i < 4; i++){
            float4 a4 = *(const float4*)(A + (size_t)(row0+ar)*K + k0 + ac + i*4);
            uint4 h4, l4;
            tf32_split(a4.x, h4.x, l4.x); tf32_split(a4.y, h4.y, l4.y);
            tf32_split(a4.z, h4.z, l4.z); tf32_split(a4.w, h4.w, l4.w);
            *(uint4*)&Ah[ar][ac+i*4] = h4;
            *(uint4*)&Al[ar][ac+i*4] = l4;
        }
        #pragma unroll
        for (int i = 0; i < 2; i++){
            float4 b4 = *(const float4*)(W + (size_t)(k0+br)*COUT + col0 + bc + i*4);
            uint4 h4, l4;
            tf32_split(b4.x, h4.x, l4.x); tf32_split(b4.y, h4.y, l4.y);
            tf32_split(b4.z, h4.z, l4.z); tf32_split(b4.w, h4.w, l4.w);
            *(uint4*)&Bh[br][bc+i*4] = h4;
            *(uint4*)&Bl[br][bc+i*4] = l4;
        }
        __syncthreads();
        #pragma unroll
        for (int ks = 0; ks < 4; ks++){
            int kb = ks*8;
            uint32_t ah[2][4], al[2][4], bh[4][2], bl[4][2];
            #pragma unroll
            for (int mi = 0; mi < 2; mi++){
                ah[mi][0] = Ah[wm+mi*16+g  ][kb+t  ]; al[mi][0] = Al[wm+mi*16+g  ][kb+t  ];
                ah[mi][1] = Ah[wm+mi*16+g+8][kb+t  ]; al[mi][1] = Al[wm+mi*16+g+8][kb+t  ];
                ah[mi][2] = Ah[wm+mi*16+g  ][kb+t+4]; al[mi][2] = Al[wm+mi*16+g  ][kb+t+4];
                ah[mi][3] = Ah[wm+mi*16+g+8][kb+t+4]; al[mi][3] = Al[wm+mi*16+g+8][kb+t+4];
            }
            #pragma unroll
            for (int ni = 0; ni < 4; ni++){
                bh[ni][0] = Bh[kb+t  ][wn+ni*8+g]; bl[ni][0] = Bl[kb+t  ][wn+ni*8+g];
                bh[ni][1] = Bh[kb+t+4][wn+ni*8+g]; bl[ni][1] = Bl[kb+t+4][wn+ni*8+g];
            }
            #pragma unroll
            for (int mi = 0; mi < 2; mi++)
                #pragma unroll
                for (int ni = 0; ni < 4; ni++){
                    float* d = acc[mi*4+ni];
                    mma_tf32(d, al[mi], bh[ni]);
                    mma_tf32(d, ah[mi], bl[ni]);
                    mma_tf32(d, ah[mi], bh[ni]);
                }
        }
        __syncthreads();
    }

    #pragma unroll
    for (int mi = 0; mi < 2; mi++){
        #pragma unroll
        for (int ni = 0; ni < 4; ni++){
            int col = col0 + wn + ni*8 + t*2;
            float b0 = bias[col], b1 = bias[col+1];
            float* d = acc[mi*4+ni];
            int r0 = row0 + wm + mi*16 + g;
            *(float2*)(C + (size_t)r0*COUT + col)     = make_float2(d[0]+b0, d[1]+b1);
            *(float2*)(C + (size_t)(r0+8)*COUT + col) = make_float2(d[2]+b0, d[3]+b1);
        }
    }
}

// ---- fused fc GEMM: A computed on the fly = combine(proj3,proj7,ffnh,coef) ----
// A element (row, cc): cc<256 -> lrelu BN(res0) + lrelu BN(ffn0); else branch 1.
// Exactly the combine_k formulas.
__device__ __forceinline__ float fuse_elem(int row, int cc){
    const size_t RC = (size_t)ROWS*COUT;
    float x, t, r, f;
    if (cc < COUT){
        x = g_proj[3*RC + (size_t)row*COUT + cc];
        t = g_coef[(0*COUT+cc)*2]*x + g_coef[(0*COUT+cc)*2+1];
        r = lrelu(t);
        x = g_ffnh[(size_t)row*COUT + cc];
        t = g_coef[(2*COUT+cc)*2]*x + g_coef[(2*COUT+cc)*2+1];
        f = lrelu(t);
    } else {
        int c = cc - COUT;
        x = g_proj[7*RC + (size_t)row*COUT + c];
        t = g_coef[(1*COUT+c)*2]*x + g_coef[(1*COUT+c)*2+1];
        r = lrelu(t);
        x = g_ffnh[RC + (size_t)row*COUT + c];
        t = g_coef[(3*COUT+c)*2]*x + g_coef[(3*COUT+c)*2+1];
        f = lrelu(t);
    }
    return r + f;
}

__global__ void __launch_bounds__(256) gemm3fc_k(const float* __restrict__ W,
                                                 const float* __restrict__ bias,
                                                 float* __restrict__ C){
    __shared__ uint32_t sm[SM_WORDS];
    uint32_t (*Ah)[36] = (uint32_t(*)[36])sm;
    uint32_t (*Al)[36] = (uint32_t(*)[36])(sm + 128*36);
    uint32_t (*Bh)[72] = (uint32_t(*)[72])(sm + 128*36*2);
    uint32_t (*Bl)[72] = (uint32_t(*)[72])(sm + 128*36*2 + 32*72);

    const int K = 2*COUT;
    int tid = threadIdx.x, lane = tid & 31, wid = tid >> 5;
    int wm = (wid & 3) * 32, wn = (wid >> 2) * 32;
    int row0 = blockIdx.y*BM, col0 = blockIdx.x*BN;
    int g = lane >> 2, t = lane & 3;

    float acc[8][4];
    #pragma unroll
    for (int i=0;i<8;i++){ acc[i][0]=0.f; acc[i][1]=0.f; acc[i][2]=0.f; acc[i][3]=0.f; }

    int ar = tid >> 1, ac = (tid & 1) * 16;
    int br = tid >> 3, bc = (tid & 7) * 8;

    for (int k0 = 0; k0 < K; k0 += BKT){
        #pragma unroll
        for (int i = 0; i < 16; i++){
            float a = fuse_elem(row0+ar, k0 + ac + i);
            uint32_t hi, lo;
            tf32_split(a, hi, lo);
            Ah[ar][ac+i] = hi;
            Al[ar][ac+i] = lo;
        }
        #pragma unroll
        for (int i = 0; i < 2; i++){
            float4 b4 = *(const float4*)(W + (size_t)(k0+br)*COUT + col0 + bc + i*4);
            uint4 h4, l4;
            tf32_split(b4.x, h4.x, l4.x); tf32_split(b4.y, h4.y, l4.y);
            tf32_split(b4.z, h4.z, l4.z); tf32_split(b4.w, h4.w, l4.w);
            *(uint4*)&Bh[br][bc+i*4] = h4;
            *(uint4*)&Bl[br][bc+i*4] = l4;
        }
        __syncthreads();
        #pragma unroll
        for (int ks = 0; ks < 4; ks++){
            int kb = ks*8;
            uint32_t ah[2][4], al[2][4], bh[4][2], bl[4][2];
            #pragma unroll
            for (int mi = 0; mi < 2; mi++){
                ah[mi][0] = Ah[wm+mi*16+g  ][kb+t  ]; al[mi][0] = Al[wm+mi*16+g  ][kb+t  ];
                ah[mi][1] = Ah[wm+mi*16+g+8][kb+t  ]; al[mi][1] = Al[wm+mi*16+g+8][kb+t  ];
                ah[mi][2] = Ah[wm+mi*16+g  ][kb+t+4]; al[mi][2] = Al[wm+mi*16+g  ][kb+t+4];
                ah[mi][3] = Ah[wm+mi*16+g+8][kb+t+4]; al[mi][3] = Al[wm+mi*16+g+8][kb+t+4];
            }
            #pragma unroll
            for (int ni = 0; ni < 4; ni++){
                bh[ni][0] = Bh[kb+t  ][wn+ni*8+g]; bl[ni][0] = Bl[kb+t  ][wn+ni*8+g];
                bh[ni][1] = Bh[kb+t+4][wn+ni*8+g]; bl[ni][1] = Bl[kb+t+4][wn+ni*8+g];
            }
            #pragma unroll
            for (int mi = 0; mi < 2; mi++)
                #pragma unroll
                for (int ni = 0; ni < 4; ni++){
                    float* d = acc[mi*4+ni];
                    mma_tf32(d, al[mi], bh[ni]);
                    mma_tf32(d, ah[mi], bl[ni]);
                    mma_tf32(d, ah[mi], bh[ni]);
                }
        }
        __syncthreads();
    }

    #pragma unroll
    for (int mi = 0; mi < 2; mi++){
        #pragma unroll
        for (int ni = 0; ni < 4; ni++){
            int col = col0 + wn + ni*8 + t*2;
            float b0 = bias[col], b1 = bias[col+1];
            float* d = acc[mi*4+ni];
            int r0 = row0 + wm + mi*16 + g;
            *(float2*)(C + (size_t)r0*COUT + col)     = make_float2(d[0]+b0, d[1]+b1);
            *(float2*)(C + (size_t)(r0+8)*COUT + col) = make_float2(d[2]+b0, d[3]+b1);
        }
    }
}

// ---------------- attention ----------------
struct AttnB { const float* q; const float* k; const float* v; const int* idx; float* ctx; };
struct AttnP { AttnB b[2]; };

__global__ void attn_k(AttnP p){
    AttnB a = p.b[blockIdx.z];
    int row = blockIdx.x;
    int bb = row / NPTS;
    __shared__ int gix[K_NN];
    if (threadIdx.x < K_NN) gix[threadIdx.x] = bb*NPTS + a.idx[(size_t)row*K_NN + threadIdx.x];
    __syncthreads();
    int c = threadIdx.x;
    float q = a.q[(size_t)row*COUT + c];
    float e[K_NN];
    float mx = -FINF;
    #pragma unroll
    for (int j = 0; j < K_NN; j++){
        float kk = a.k[(size_t)gix[j]*COUT + c];
        float ee = (q - kk) * 0.0625f;
        e[j] = ee;
        mx = fmaxf(mx, ee);
    }
    float s = 0.f;
    #pragma unroll
    for (int j = 0; j < K_NN; j++){ e[j] = expf(e[j] - mx); s += e[j]; }
    float inv = 1.f / s;
    float best = -FINF;
    #pragma unroll
    for (int j = 0; j < K_NN; j++){
        float att = e[j]*inv - 1.f;
        float vv = a.v[(size_t)gix[j]*COUT + c];
        best = fmaxf(best, att*vv);
    }
    a.ctx[(size_t)row*COUT + c] = best;
}

// ---------------- BatchNorm stats: deterministic two-stage ----------------
struct StatB { const float* x; int slot; };
struct StatP { StatB b[4]; };

__global__ void bn_stats_k(StatP p){
    StatB sb = p.b[blockIdx.z];
    int c = threadIdx.x;
    int r0 = blockIdx.x * (ROWS/64);
    float s = 0.f, sq = 0.f;
    for (int r = r0; r < r0 + ROWS/64; r++){
        float v = sb.x[(size_t)r*COUT + c];
        s += v; sq += v*v;
    }
    float* pp = g_part + (size_t)(sb.slot*64 + blockIdx.x)*2*COUT;
    pp[c] = s; pp[COUT + c] = sq;
}

struct FinB { const float* gamma; const float* beta; int slot; };
struct FinP { FinB b[4]; };

__global__ void bn_final_k(FinP p){
    FinB f = p.b[blockIdx.x];
    int c = threadIdx.x;
    float s = 0.f, sq = 0.f;
    for (int i = 0; i < 64; i++){
        const float* pp = g_part + (size_t)(f.slot*64 + i)*2*COUT;
        s += pp[c]; sq += pp[COUT + c];
    }
    float mean = s * (1.f/ROWS);
    float var  = sq * (1.f/ROWS) - mean*mean;
    float rstd = rsqrtf(var + 1e-5f);
    float aa = f.gamma[c] * rstd;
    g_coef[(f.slot*COUT + c)*2 + 0] = aa;
    g_coef[(f.slot*COUT + c)*2 + 1] = f.beta[c] - mean*aa;
}

// ---------------- final BN + leaky relu ----------------
__global__ void final_k(float* __restrict__ out){
    int row = blockIdx.x, c = threadIdx.x;
    float x = g_mergeh[(size_t)row*COUT + c];
    float t = g_coef[(4*COUT+c)*2]*x + g_coef[(4*COUT+c)*2+1];
    out[(size_t)row*COUT + c] = lrelu(t);
}

// ---------------- host ----------------
extern "C" void kernel_launch(void* const* d_in, const int* in_sizes, int n_in,
                              void* d_out, int out_size){
    const float* xyz    = (const float*)d_in[0];
    const float* bxyz   = (const float*)d_in[1];
    const float* feat   = (const float*)d_in[2];
    const float* qW     = (const float*)d_in[3];
    const float* qb     = (const float*)d_in[4];
    const float* kW     = (const float*)d_in[5];
    const float* kb     = (const float*)d_in[6];
    const float* vW     = (const float*)d_in[7];
    const float* vb     = (const float*)d_in[8];
    const float* rW     = (const float*)d_in[9];
    const float* rb     = (const float*)d_in[10];
    const float* rg     = (const float*)d_in[11];
    const float* rbeta  = (const float*)d_in[12];
    const float* fW     = (const float*)d_in[13];
    const float* fb     = (const float*)d_in[14];
    const float* fg     = (const float*)d_in[15];
    const float* fbeta  = (const float*)d_in[16];
    const float* fcW    = (const float*)d_in[17];
    const float* fcb    = (const float*)d_in[18];
    const float* fcg    = (const float*)d_in[19];
    const float* fcbeta = (const float*)d_in[20];

    float *proj, *ctx, *ffnh, *mergeh;
    int *idx0, *idx1;
    cudaGetSymbolAddress((void**)&proj,   g_proj);
    cudaGetSymbolAddress((void**)&ctx,    g_ctx);
    cudaGetSymbolAddress((void**)&ffnh,   g_ffnh);
    cudaGetSymbolAddress((void**)&mergeh, g_mergeh);
    cudaGetSymbolAddress((void**)&idx0,   g_idx0);
    cudaGetSymbolAddress((void**)&idx1,   g_idx1);

    // streams/events created once (outside capture), reused identically each call.
    static cudaStream_t s1 = nullptr, s2 = nullptr;
    static cudaEvent_t ev_root, ev1, ev2;
    if (!s1){
        cudaStreamCreate(&s1);
        cudaStreamCreate(&s2);
        cudaEventCreateWithFlags(&ev_root, cudaEventDisableTiming);
        cudaEventCreateWithFlags(&ev1,     cudaEventDisableTiming);
        cudaEventCreateWithFlags(&ev2,     cudaEventDisableTiming);
    }

    const size_t RC = (size_t)ROWS*COUT;

    // fork
    cudaEventRecord(ev_root, 0);
    cudaStreamWaitEvent(s1, ev_root, 0);
    cudaStreamWaitEvent(s2, ev_root, 0);

    // s1: xyz KNN (independent)
    knn_xyz_k<<<ROWS, 256, 0, s1>>>(xyz, bxyz);
    cudaEventRecord(ev1, s1);

    // s2: projection GEMMs + residual BN stats (independent of dist chain)
    {
        GemmP p; p.K = CIN;
        const float* Ws[8] = {qW, kW, vW, rW,
                              qW + CIN*COUT, kW + CIN*COUT, vW + CIN*COUT, rW + CIN*COUT};
        const float* Bs[8] = {qb, kb, vb, rb, qb + COUT, kb + COUT, vb + COUT, rb + COUT};
        for (int i = 0; i < 8; i++){ p.b[i].A = feat; p.b[i].W = Ws[i]; p.b[i].bias = Bs[i]; p.b[i].C = proj + (size_t)i*RC; }
        gemm3_k<<<dim3(COUT/BN, ROWS/BM, 8), 256, 0, s2>>>(p);
    }
    {
        StatP s; s.b[0] = {proj + 3*RC, 0}; s.b[1] = {proj + 7*RC, 1};
        bn_stats_k<<<dim3(64,1,2), 256, 0, s2>>>(s);
    }
    cudaEventRecord(ev2, s2);

    // main: norms -> dist (streaming stores) -> feature select
    norms_k<<<ROWS/8, 256>>>(feat);
    dist_gemm_k<<<dim3(NPTS/128, NPTS/128, BATCH), 256>>>(feat);
    select_feat_k<<<ROWS, 256>>>();

    // join
    cudaStreamWaitEvent(0, ev1, 0);
    cudaStreamWaitEvent(0, ev2, 0);

    {
        AttnP a;
        a.b[0] = {proj + 0*RC, proj + 1*RC, proj + 2*RC, idx0, ctx};
        a.b[1] = {proj + 4*RC, proj + 5*RC, proj + 6*RC, idx1, ctx + RC};
        attn_k<<<dim3(ROWS,1,2), 256>>>(a);
    }

    {
        GemmP p; p.K = COUT;
        p.b[0] = {ctx,      fW,             fb,        ffnh};
        p.b[1] = {ctx + RC, fW + COUT*COUT, fb + COUT, ffnh + RC};
        gemm3_k<<<dim3(COUT/BN, ROWS/BM, 2), 256>>>(p);
    }

    {
        StatP s; s.b[0] = {ffnh, 2}; s.b[1] = {ffnh + RC, 3};
        bn_stats_k<<<dim3(64,1,2), 256>>>(s);
    }

    {
        FinP f;
        f.b[0] = {rg,        rbeta,        0};
        f.b[1] = {rg + COUT, rbeta + COUT, 1};
        f.b[2] = {fg,        fbeta,        2};
        f.b[3] = {fg + COUT, fbeta + COUT, 3};
        bn_final_k<<<4, 256>>>(f);
    }

    // fused combine + fc GEMM (A computed on the fly)
    gemm3fc_k<<<dim3(COUT/BN, ROWS/BM), 256>>>(fcW, fcb, mergeh);

    {
        StatP s; s.b[0] = {mergeh, 4};
        bn_stats_k<<<dim3(64,1,1), 256>>>(s);
        FinP f; f.b[0] = {fcg, fcbeta, 4};
        bn_final_k<<<1, 256>>>(f);
    }

    final_k<<<ROWS, 256>>>((float*)d_out);
}

// round 15
// speedup vs baseline: 1.1797x; 1.1797x over previous
#include <cuda_runtime.h>
#include <cstdint>
#include <cstddef>

#define BATCH 4
#define NPTS  2048
#define ROWS  (BATCH*NPTS)   // 8192
#define CIN   128
#define COUT  256
#define K_NN  32

#define FINF __int_as_float(0x7f800000)
typedef unsigned long long ull;

// ---------------- scratch ----------------
__device__ float g_norms[ROWS];
__device__ float g_dist[(size_t)BATCH*NPTS*NPTS];          // 64 MB
__device__ int   g_idx0[ROWS*K_NN];
__device__ int   g_idx1[ROWS*K_NN];
__device__ float g_proj[(size_t)8*ROWS*COUT];              // q0,k0,v0,r0,q1,k1,v1,r1
__device__ float g_ctx[(size_t)2*ROWS*COUT];
__device__ float g_ffnh[(size_t)2*ROWS*COUT];
__device__ float g_mcat[(size_t)ROWS*2*COUT];
__device__ float g_mergeh[(size_t)ROWS*COUT];
__device__ float g_part[5*64*2*COUT];
__device__ float g_coef[5*COUT*2];

__device__ __forceinline__ float lrelu(float x){ return x > 0.f ? x : 0.2f*x; }

__device__ __forceinline__ uint32_t fkey(float f){
    uint32_t b = __float_as_uint(f);
    return b ^ (uint32_t)(((int)b >> 31) | 0x80000000);
}

// mask-based tf32 split (validated R7): hi = tf32 truncation, lo = exact residual.
__device__ __forceinline__ void tf32_split(float x, uint32_t& hi, uint32_t& lo){
    hi = __float_as_uint(x) & 0xFFFFE000u;
    lo = __float_as_uint(x - __uint_as_float(hi));
}

// ---------------- row squared norms of feature (one warp per row) ----------------
__global__ void norms_k(const float* __restrict__ feat){
    int w = (blockIdx.x*blockDim.x + threadIdx.x) >> 5;
    int lane = threadIdx.x & 31;
    if (w >= ROWS) return;
    float4 f4 = ((const float4*)(feat + (size_t)w*CIN))[lane];
    float s = f4.x*f4.x + f4.y*f4.y + f4.z*f4.z + f4.w*f4.w;
    #pragma unroll
    for (int o=16;o;o>>=1) s += __shfl_xor_sync(0xffffffffu, s, o);
    if (!lane) g_norms[w] = s;
}

// ---------------- register-key radix select (validated R10) ----------------
__device__ void select32_reg(const ull* __restrict__ k64, int* __restrict__ out){
    __shared__ int h[256];
    __shared__ int sc[256];
    __shared__ ull s_prefix, s_bound;
    __shared__ int s_need, s_done, s_cnt;
    int tid = threadIdx.x;
    if (tid == 0){ s_prefix = 0; s_need = K_NN; s_done = 0; s_cnt = 0; }
    int shift = 40;
    __syncthreads();
    while (true){
        h[tid] = 0;
        __syncthreads();
        ull pref = s_prefix;
        int need = s_need;
        #pragma unroll
        for (int i = 0; i < 8; i++){
            if ((k64[i] >> (shift + 8)) == pref)
                atomicAdd(&h[(int)((k64[i] >> shift) & 0xFF)], 1);
        }
        __syncthreads();
        int hv = h[tid];
        sc[tid] = hv;
        __syncthreads();
        #pragma unroll
        for (int o = 1; o < 256; o <<= 1){
            int u = (tid >= o) ? sc[tid - o] : 0;
            __syncthreads();
            sc[tid] += u;
            __syncthreads();
        }
        int incl = sc[tid], excl = incl - hv;
        if (excl < need && incl >= need){
            int nn = need - excl;
            if (hv == nn){
                s_bound = ((((pref << 8) | (ull)tid) + 1ull) << shift);
                s_done = 1;
            } else {
                s_prefix = (pref << 8) | (ull)tid;
                s_need = nn;
            }
        }
        __syncthreads();
        if (s_done) break;
        shift -= 8;
    }
    ull bound = s_bound;
    #pragma unroll
    for (int i = 0; i < 8; i++){
        if (k64[i] < bound){
            int p = atomicAdd(&s_cnt, 1);
            out[p] = (int)(k64[i] & 0xFFFFull);
        }
    }
}

// ---------------- xyz KNN: fused distance + reg-key selection ----------------
__global__ void knn_xyz_k(const float* __restrict__ xyz, const float* __restrict__ bxyz){
    __shared__ float sp[NPTS*3];
    int row = blockIdx.x;
    int b = row / NPTS;
    int tid = threadIdx.x;
    const float* bp = bxyz + (size_t)b*NPTS*3;
    for (int i = tid; i < NPTS*3; i += 256) sp[i] = bp[i];
    float qx = xyz[(size_t)row*3+0], qy = xyz[(size_t)row*3+1], qz = xyz[(size_t)row*3+2];
    float qn = qx*qx + qy*qy + qz*qz;
    __syncthreads();
    ull k64[8];
    #pragma unroll
    for (int i = 0; i < 8; i++){
        int m = tid + i*256;
        float px = sp[m*3+0], py = sp[m*3+1], pz = sp[m*3+2];
        float pn = px*px + py*py + pz*pz;
        float d = qn + pn - 2.f*(qx*px + qy*py + qz*pz);
        k64[i] = ((ull)fkey(d) << 16) | (ull)m;
    }
    select32_reg(k64, g_idx0 + (size_t)row*K_NN);
}

// ---------------- feature KNN selection ----------------
__global__ void select_feat_k(){
    int row = blockIdx.x;
    int tid = threadIdx.x;
    const float4* dr = (const float4*)(g_dist + (size_t)row*NPTS);
    ull k64[8];
    #pragma unroll
    for (int i = 0; i < 2; i++){
        float4 d4 = dr[i*256 + tid];
        int m = (i*256 + tid)*4;
        k64[i*4+0] = ((ull)fkey(d4.x) << 16) | (ull)(m+0);
        k64[i*4+1] = ((ull)fkey(d4.y) << 16) | (ull)(m+1);
        k64[i*4+2] = ((ull)fkey(d4.z) << 16) | (ull)(m+2);
        k64[i*4+3] = ((ull)fkey(d4.w) << 16) | (ull)(m+3);
    }
    select32_reg(k64, g_idx1 + (size_t)row*K_NN);
}

// ---------------- feature pairwise distance GEMM (fp32 SIMT — REQUIRED precision) ------
// 128x128 tile, 8x8 accum, conflict-free B mapping (tx + 16*j). R13-validated.
__global__ void __launch_bounds__(256) dist_gemm_k(const float* __restrict__ feat){
    int bz = blockIdx.z;
    const float* A = feat + (size_t)bz*NPTS*CIN;
    __shared__ float As[16][136];
    __shared__ float Bs[16][136];
    int tid = threadIdx.x, tx = tid & 15, ty = tid >> 4;
    int row0 = blockIdx.y*128, col0 = blockIdx.x*128;
    float acc[8][8] = {};
    int ar = tid >> 1, ac = (tid & 1) * 8;
    for (int k0 = 0; k0 < CIN; k0 += 16){
        float4 a4 = *(const float4*)(A + (size_t)(row0+ar)*CIN + k0 + ac);
        float4 a5 = *(const float4*)(A + (size_t)(row0+ar)*CIN + k0 + ac + 4);
        As[ac+0][ar]=a4.x; As[ac+1][ar]=a4.y; As[ac+2][ar]=a4.z; As[ac+3][ar]=a4.w;
        As[ac+4][ar]=a5.x; As[ac+5][ar]=a5.y; As[ac+6][ar]=a5.z; As[ac+7][ar]=a5.w;
        float4 b4 = *(const float4*)(A + (size_t)(col0+ar)*CIN + k0 + ac);
        float4 b5 = *(const float4*)(A + (size_t)(col0+ar)*CIN + k0 + ac + 4);
        Bs[ac+0][ar]=b4.x; Bs[ac+1][ar]=b4.y; Bs[ac+2][ar]=b4.z; Bs[ac+3][ar]=b4.w;
        Bs[ac+4][ar]=b5.x; Bs[ac+5][ar]=b5.y; Bs[ac+6][ar]=b5.z; Bs[ac+7][ar]=b5.w;
        __syncthreads();
        #pragma unroll
        for (int kk = 0; kk < 16; kk++){
            float av[8], bv[8];
            #pragma unroll
            for (int i=0;i<8;i++) av[i] = As[kk][ty*8+i];
            #pragma unroll
            for (int j=0;j<8;j++) bv[j] = Bs[kk][tx + 16*j];
            #pragma unroll
            for (int i=0;i<8;i++)
                #pragma unroll
                for (int j=0;j<8;j++) acc[i][j] += av[i]*bv[j];
        }
        __syncthreads();
    }
    float* D = g_dist + (size_t)bz*NPTS*NPTS;
    const float* qn = g_norms + bz*NPTS;
    #pragma unroll
    for (int i=0;i<8;i++){
        int n = row0 + ty*8 + i;
        float qnn = qn[n];
        #pragma unroll
        for (int j=0;j<8;j++){
            int m = col0 + tx + 16*j;
            D[(size_t)n*NPTS + m] = qnn + qn[m] - 2.f*acc[i][j];
        }
    }
}

// ================= 3xTF32 tensor-core GEMM (validated R7) =================
#define BM 128
#define BN 64
#define BKT 32
#define SM_WORDS (128*36*2 + 32*72*2)

struct GemmB { const float* A; const float* W; const float* bias; float* C; };
struct GemmP { GemmB b[8]; int K; };

__device__ __forceinline__ void mma_tf32(float* d, const uint32_t* a, const uint32_t* b){
    asm volatile(
        "mma.sync.aligned.m16n8k8.row.col.f32.tf32.tf32.f32 "
        "{%0,%1,%2,%3}, {%4,%5,%6,%7}, {%8,%9}, {%0,%1,%2,%3};\n"
        : "+f"(d[0]), "+f"(d[1]), "+f"(d[2]), "+f"(d[3])
        : "r"(a[0]), "r"(a[1]), "r"(a[2]), "r"(a[3]), "r"(b[0]), "r"(b[1]));
}

__global__ void __launch_bounds__(256) gemm3_k(GemmP p){
    __shared__ uint32_t sm[SM_WORDS];
    uint32_t (*Ah)[36] = (uint32_t(*)[36])sm;
    uint32_t (*Al)[36] = (uint32_t(*)[36])(sm + 128*36);
    uint32_t (*Bh)[72] = (uint32_t(*)[72])(sm + 128*36*2);
    uint32_t (*Bl)[72] = (uint32_t(*)[72])(sm + 128*36*2 + 32*72);

    int z = blockIdx.z;
    const float* A = p.b[z].A;
    const float* W = p.b[z].W;
    const float* bias = p.b[z].bias;
    float* C = p.b[z].C;
    int K = p.K;

    int tid = threadIdx.x, lane = tid & 31, wid = tid >> 5;
    int wm = (wid & 3) * 32, wn = (wid >> 2) * 32;
    int row0 = blockIdx.y*BM, col0 = blockIdx.x*BN;
    int g = lane >> 2, t = lane & 3;

    float acc[8][4];
    #pragma unroll
    for (int i=0;i<8;i++){ acc[i][0]=0.f; acc[i][1]=0.f; acc[i][2]=0.f; acc[i][3]=0.f; }

    int ar = tid >> 1, ac = (tid & 1) * 16;
    int br = tid >> 3, bc = (tid & 7) * 8;

    for (int k0 = 0; k0 < K; k0 += BKT){
        #pragma unroll
        for (int i = 0; i < 4; i++){
            float4 a4 = *(const float4*)(A + (size_t)(row0+ar)*K + k0 + ac + i*4);
            uint4 h4, l4;
            tf32_split(a4.x, h4.x, l4.x); tf32_split(a4.y, h4.y, l4.y);
            tf32_split(a4.z, h4.z, l4.z); tf32_split(a4.w, h4.w, l4.w);
            *(uint4*)&Ah[ar][ac+i*4] = h4;
            *(uint4*)&Al[ar][ac+i*4] = l4;
        }
        #pragma unroll
        for (int i = 0; i < 2; i++){
            float4 b4 = *(const float4*)(W + (size_t)(k0+br)*COUT + col0 + bc + i*4);
            uint4 h4, l4;
            tf32_split(b4.x, h4.x, l4.x); tf32_split(b4.y, h4.y, l4.y);
            tf32_split(b4.z, h4.z, l4.z); tf32_split(b4.w, h4.w, l4.w);
            *(uint4*)&Bh[br][bc+i*4] = h4;
            *(uint4*)&Bl[br][bc+i*4] = l4;
        }
        __syncthreads();
        #pragma unroll
        for (int ks = 0; ks < 4; ks++){
            int kb = ks*8;
            uint32_t ah[2][4], al[2][4], bh[4][2], bl[4][2];
            #pragma unroll
            for (int mi = 0; mi < 2; mi++){
                ah[mi][0] = Ah[wm+mi*16+g  ][kb+t  ]; al[mi][0] = Al[wm+mi*16+g  ][kb+t  ];
                ah[mi][1] = Ah[wm+mi*16+g+8][kb+t  ]; al[mi][1] = Al[wm+mi*16+g+8][kb+t  ];
                ah[mi][2] = Ah[wm+mi*16+g  ][kb+t+4]; al[mi][2] = Al[wm+mi*16+g  ][kb+t+4];
                ah[mi][3] = Ah[wm+mi*16+g+8][kb+t+4]; al[mi][3] = Al[wm+mi*16+g+8][kb+t+4];
            }
            #pragma unroll
            for (int ni = 0; ni < 4; ni++){
                bh[ni][0] = Bh[kb+t  ][wn+ni*8+g]; bl[ni][0] = Bl[kb+t  ][wn+ni*8+g];
                bh[ni][1] = Bh[kb+t+4][wn+ni*8+g]; bl[ni][1] = Bl[kb+t+4][wn+ni*8+g];
            }
            #pragma unroll
            for (int mi = 0; mi < 2; mi++)
                #pragma unroll
                for (int ni = 0; ni < 4; ni++){
                    float* d = acc[mi*4+ni];
                    mma_tf32(d, al[mi], bh[ni]);
                    mma_tf32(d, ah[mi], bl[ni]);
                    mma_tf32(d, ah[mi], bh[ni]);
                }
        }
        __syncthreads();
    }

    #pragma unroll
    for (int mi = 0; mi < 2; mi++){
        #pragma unroll
        for (int ni = 0; ni < 4; ni++){
            int col = col0 + wn + ni*8 + t*2;
            float b0 = bias[col], b1 = bias[col+1];
            float* d = acc[mi*4+ni];
            int r0 = row0 + wm + mi*16 + g;
            *(float2*)(C + (size_t)r0*COUT + col)     = make_float2(d[0]+b0, d[1]+b1);
            *(float2*)(C + (size_t)(r0+8)*COUT + col) = make_float2(d[2]+b0, d[3]+b1);
        }
    }
}

// ---------------- attention (single branch, parameterized) ----------------
__global__ void attn_k(const float* __restrict__ q_, const float* __restrict__ k_,
                       const float* __restrict__ v_, const int* __restrict__ idx_,
                       float* __restrict__ ctx_){
    int row = blockIdx.x;
    int bb = row / NPTS;
    __shared__ int gix[K_NN];
    if (threadIdx.x < K_NN) gix[threadIdx.x] = bb*NPTS + idx_[(size_t)row*K_NN + threadIdx.x];
    __syncthreads();
    int c = threadIdx.x;
    float q = q_[(size_t)row*COUT + c];
    float e[K_NN];
    float mx = -FINF;
    #pragma unroll
    for (int j = 0; j < K_NN; j++){
        float kk = k_[(size_t)gix[j]*COUT + c];
        float ee = (q - kk) * 0.0625f;
        e[j] = ee;
        mx = fmaxf(mx, ee);
    }
    float s = 0.f;
    #pragma unroll
    for (int j = 0; j < K_NN; j++){ e[j] = expf(e[j] - mx); s += e[j]; }
    float inv = 1.f / s;
    float best = -FINF;
    #pragma unroll
    for (int j = 0; j < K_NN; j++){
        float att = e[j]*inv - 1.f;
        float vv = v_[(size_t)gix[j]*COUT + c];
        best = fmaxf(best, att*vv);
    }
    ctx_[(size_t)row*COUT + c] = best;
}

// ---------------- BatchNorm stats: deterministic two-stage ----------------
struct StatB { const float* x; int slot; };
struct StatP { StatB b[4]; };

__global__ void bn_stats_k(StatP p){
    StatB sb = p.b[blockIdx.z];
    int c = threadIdx.x;
    int r0 = blockIdx.x * (ROWS/64);
    float s = 0.f, sq = 0.f;
    for (int r = r0; r < r0 + ROWS/64; r++){
        float v = sb.x[(size_t)r*COUT + c];
        s += v; sq += v*v;
    }
    float* pp = g_part + (size_t)(sb.slot*64 + blockIdx.x)*2*COUT;
    pp[c] = s; pp[COUT + c] = sq;
}

struct FinB { const float* gamma; const float* beta; int slot; };
struct FinP { FinB b[4]; };

__global__ void bn_final_k(FinP p){
    FinB f = p.b[blockIdx.x];
    int c = threadIdx.x;
    float s = 0.f, sq = 0.f;
    for (int i = 0; i < 64; i++){
        const float* pp = g_part + (size_t)(f.slot*64 + i)*2*COUT;
        s += pp[c]; sq += pp[COUT + c];
    }
    float mean = s * (1.f/ROWS);
    float var  = sq * (1.f/ROWS) - mean*mean;
    float rstd = rsqrtf(var + 1e-5f);
    float aa = f.gamma[c] * rstd;
    g_coef[(f.slot*COUT + c)*2 + 0] = aa;
    g_coef[(f.slot*COUT + c)*2 + 1] = f.beta[c] - mean*aa;
}

// ---------------- combine residual + ffn per branch ----------------
__global__ void combine_k(){
    int row = blockIdx.x, c = threadIdx.x;
    const size_t RC = (size_t)ROWS*COUT;
    float x  = g_proj[3*RC + (size_t)row*COUT + c];
    float t  = g_coef[(0*COUT+c)*2]*x + g_coef[(0*COUT+c)*2+1];
    float r0 = lrelu(t);
    x = g_ffnh[(size_t)row*COUT + c];
    t = g_coef[(2*COUT+c)*2]*x + g_coef[(2*COUT+c)*2+1];
    float f0 = lrelu(t);
    g_mcat[(size_t)row*2*COUT + c] = r0 + f0;
    x = g_proj[7*RC + (size_t)row*COUT + c];
    t = g_coef[(1*COUT+c)*2]*x + g_coef[(1*COUT+c)*2+1];
    float r1 = lrelu(t);
    x = g_ffnh[RC + (size_t)row*COUT + c];
    t = g_coef[(3*COUT+c)*2]*x + g_coef[(3*COUT+c)*2+1];
    float f1 = lrelu(t);
    g_mcat[(size_t)row*2*COUT + COUT + c] = r1 + f1;
}

// ---------------- final BN + leaky relu ----------------
__global__ void final_k(float* __restrict__ out){
    int row = blockIdx.x, c = threadIdx.x;
    float x = g_mergeh[(size_t)row*COUT + c];
    float t = g_coef[(4*COUT+c)*2]*x + g_coef[(4*COUT+c)*2+1];
    out[(size_t)row*COUT + c] = lrelu(t);
}

// ---------------- host ----------------
extern "C" void kernel_launch(void* const* d_in, const int* in_sizes, int n_in,
                              void* d_out, int out_size){
    const float* xyz    = (const float*)d_in[0];
    const float* bxyz   = (const float*)d_in[1];
    const float* feat   = (const float*)d_in[2];
    const float* qW     = (const float*)d_in[3];
    const float* qb     = (const float*)d_in[4];
    const float* kW     = (const float*)d_in[5];
    const float* kb     = (const float*)d_in[6];
    const float* vW     = (const float*)d_in[7];
    const float* vb     = (const float*)d_in[8];
    const float* rW     = (const float*)d_in[9];
    const float* rb     = (const float*)d_in[10];
    const float* rg     = (const float*)d_in[11];
    const float* rbeta  = (const float*)d_in[12];
    const float* fW     = (const float*)d_in[13];
    const float* fb     = (const float*)d_in[14];
    const float* fg     = (const float*)d_in[15];
    const float* fbeta  = (const float*)d_in[16];
    const float* fcW    = (const float*)d_in[17];
    const float* fcb    = (const float*)d_in[18];
    const float* fcg    = (const float*)d_in[19];
    const float* fcbeta = (const float*)d_in[20];

    float *proj, *ctx, *ffnh, *mcat, *mergeh;
    int *idx0, *idx1;
    cudaGetSymbolAddress((void**)&proj,   g_proj);
    cudaGetSymbolAddress((void**)&ctx,    g_ctx);
    cudaGetSymbolAddress((void**)&ffnh,   g_ffnh);
    cudaGetSymbolAddress((void**)&mcat,   g_mcat);
    cudaGetSymbolAddress((void**)&mergeh, g_mergeh);
    cudaGetSymbolAddress((void**)&idx0,   g_idx0);
    cudaGetSymbolAddress((void**)&idx1,   g_idx1);

    // streams/events created once (outside capture), reused identically each call.
    static cudaStream_t s1 = nullptr, s2 = nullptr;
    static cudaEvent_t ev_root, ev1, ev2;
    if (!s1){
        cudaStreamCreate(&s1);
        cudaStreamCreate(&s2);
        cudaEventCreateWithFlags(&ev_root, cudaEventDisableTiming);
        cudaEventCreateWithFlags(&ev1,     cudaEventDisableTiming);
        cudaEventCreateWithFlags(&ev2,     cudaEventDisableTiming);
    }

    const size_t RC = (size_t)ROWS*COUT;

    // fork
    cudaEventRecord(ev_root, 0);
    cudaStreamWaitEvent(s1, ev_root, 0);
    cudaStreamWaitEvent(s2, ev_root, 0);

    // s1: xyz KNN
    knn_xyz_k<<<ROWS, 256, 0, s1>>>(xyz, bxyz);
    cudaEventRecord(ev1, s1);

    // s2: proj GEMMs -> res stats -> (wait idx0) -> attn0 -> ffn0 -> ffn0 stats
    {
        GemmP p; p.K = CIN;
        const float* Ws[8] = {qW, kW, vW, rW,
                              qW + CIN*COUT, kW + CIN*COUT, vW + CIN*COUT, rW + CIN*COUT};
        const float* Bs[8] = {qb, kb, vb, rb, qb + COUT, kb + COUT, vb + COUT, rb + COUT};
        for (int i = 0; i < 8; i++){ p.b[i].A = feat; p.b[i].W = Ws[i]; p.b[i].bias = Bs[i]; p.b[i].C = proj + (size_t)i*RC; }
        gemm3_k<<<dim3(COUT/BN, ROWS/BM, 8), 256, 0, s2>>>(p);
    }
    {
        StatP s; s.b[0] = {proj + 3*RC, 0}; s.b[1] = {proj + 7*RC, 1};
        bn_stats_k<<<dim3(64,1,2), 256, 0, s2>>>(s);
    }
    cudaStreamWaitEvent(s2, ev1, 0);
    attn_k<<<ROWS, 256, 0, s2>>>(proj + 0*RC, proj + 1*RC, proj + 2*RC, idx0, ctx);
    {
        GemmP p; p.K = COUT;
        p.b[0] = {ctx, fW, fb, ffnh};
        gemm3_k<<<dim3(COUT/BN, ROWS/BM, 1), 256, 0, s2>>>(p);
    }
    {
        StatP s; s.b[0] = {ffnh, 2};
        bn_stats_k<<<dim3(64,1,1), 256, 0, s2>>>(s);
    }
    cudaEventRecord(ev2, s2);

    // main: norms -> dist -> select -> attn1 -> ffn1 -> stats3
    norms_k<<<ROWS/8, 256>>>(feat);
    dist_gemm_k<<<dim3(NPTS/128, NPTS/128, BATCH), 256>>>(feat);
    select_feat_k<<<ROWS, 256>>>();
    attn_k<<<ROWS, 256>>>(proj + 4*RC, proj + 5*RC, proj + 6*RC, idx1, ctx + RC);
    {
        GemmP p; p.K = COUT;
        p.b[0] = {ctx + RC, fW + COUT*COUT, fb + COUT, ffnh + RC};
        gemm3_k<<<dim3(COUT/BN, ROWS/BM, 1), 256>>>(p);
    }
    {
        StatP s; s.b[0] = {ffnh + RC, 3};
        bn_stats_k<<<dim3(64,1,1), 256>>>(s);
    }

    // join branch-0 chain
    cudaStreamWaitEvent(0, ev2, 0);

    {
        FinP f;
        f.b[0] = {rg,        rbeta,        0};
        f.b[1] = {rg + COUT, rbeta + COUT, 1};
        f.b[2] = {fg,        fbeta,        2};
        f.b[3] = {fg + COUT, fbeta + COUT, 3};
        bn_final_k<<<4, 256>>>(f);
    }

    combine_k<<<ROWS, 256>>>();

    {
        GemmP p; p.K = 2*COUT;
        p.b[0] = {mcat, fcW, fcb, mergeh};
        gemm3_k<<<dim3(COUT/BN, ROWS/BM, 1), 256>>>(p);
    }

    {
        StatP s; s.b[0] = {mergeh, 4};
        bn_stats_k<<<dim3(64,1,1), 256>>>(s);
        FinP f; f.b[0] = {fcg, fcbeta, 4};
        bn_final_k<<<1, 256>>>(f);
    }

    final_k<<<ROWS, 256>>>((float*)d_out);
}

// round 16
// speedup vs baseline: 1.2000x; 1.0172x over previous
#include <cuda_runtime.h>
#include <cstdint>
#include <cstddef>

#define BATCH 4
#define NPTS  2048
#define ROWS  (BATCH*NPTS)   // 8192
#define CIN   128
#define COUT  256
#define K_NN  32

#define FINF __int_as_float(0x7f800000)
typedef unsigned long long ull;

// ---------------- scratch ----------------
__device__ float g_norms[ROWS];
__device__ float g_dist[(size_t)BATCH*NPTS*NPTS];          // 64 MB
__device__ int   g_idx0[ROWS*K_NN];
__device__ int   g_idx1[ROWS*K_NN];
__device__ float g_proj[(size_t)8*ROWS*COUT];              // q0,k0,v0,r0,q1,k1,v1,r1
__device__ float g_ctx[(size_t)2*ROWS*COUT];
__device__ float g_ffnh[(size_t)2*ROWS*COUT];
__device__ float g_mcat[(size_t)ROWS*2*COUT];
__device__ float g_mergeh[(size_t)ROWS*COUT];
__device__ float g_part[5*64*2*COUT];
__device__ float g_coef[5*COUT*2];

__device__ __forceinline__ float lrelu(float x){ return x > 0.f ? x : 0.2f*x; }

__device__ __forceinline__ uint32_t fkey(float f){
    uint32_t b = __float_as_uint(f);
    return b ^ (uint32_t)(((int)b >> 31) | 0x80000000);
}

// mask-based tf32 split (validated R7): hi = tf32 truncation, lo = exact residual.
__device__ __forceinline__ void tf32_split(float x, uint32_t& hi, uint32_t& lo){
    hi = __float_as_uint(x) & 0xFFFFE000u;
    lo = __float_as_uint(x - __uint_as_float(hi));
}

// ---------------- row squared norms of feature (one warp per row) ----------------
__global__ void norms_k(const float* __restrict__ feat){
    int w = (blockIdx.x*blockDim.x + threadIdx.x) >> 5;
    int lane = threadIdx.x & 31;
    if (w >= ROWS) return;
    float4 f4 = ((const float4*)(feat + (size_t)w*CIN))[lane];
    float s = f4.x*f4.x + f4.y*f4.y + f4.z*f4.z + f4.w*f4.w;
    #pragma unroll
    for (int o=16;o;o>>=1) s += __shfl_xor_sync(0xffffffffu, s, o);
    if (!lane) g_norms[w] = s;
}

// ---------------- register-key radix select (validated R10) ----------------
__device__ void select32_reg(const ull* __restrict__ k64, int* __restrict__ out){
    __shared__ int h[256];
    __shared__ int sc[256];
    __shared__ ull s_prefix, s_bound;
    __shared__ int s_need, s_done, s_cnt;
    int tid = threadIdx.x;
    if (tid == 0){ s_prefix = 0; s_need = K_NN; s_done = 0; s_cnt = 0; }
    int shift = 40;
    __syncthreads();
    while (true){
        h[tid] = 0;
        __syncthreads();
        ull pref = s_prefix;
        int need = s_need;
        #pragma unroll
        for (int i = 0; i < 8; i++){
            if ((k64[i] >> (shift + 8)) == pref)
                atomicAdd(&h[(int)((k64[i] >> shift) & 0xFF)], 1);
        }
        __syncthreads();
        int hv = h[tid];
        sc[tid] = hv;
        __syncthreads();
        #pragma unroll
        for (int o = 1; o < 256; o <<= 1){
            int u = (tid >= o) ? sc[tid - o] : 0;
            __syncthreads();
            sc[tid] += u;
            __syncthreads();
        }
        int incl = sc[tid], excl = incl - hv;
        if (excl < need && incl >= need){
            int nn = need - excl;
            if (hv == nn){
                s_bound = ((((pref << 8) | (ull)tid) + 1ull) << shift);
                s_done = 1;
            } else {
                s_prefix = (pref << 8) | (ull)tid;
                s_need = nn;
            }
        }
        __syncthreads();
        if (s_done) break;
        shift -= 8;
    }
    ull bound = s_bound;
    #pragma unroll
    for (int i = 0; i < 8; i++){
        if (k64[i] < bound){
            int p = atomicAdd(&s_cnt, 1);
            out[p] = (int)(k64[i] & 0xFFFFull);
        }
    }
}

// ---------------- xyz KNN: fused distance + reg-key selection ----------------
__global__ void knn_xyz_k(const float* __restrict__ xyz, const float* __restrict__ bxyz){
    __shared__ float sp[NPTS*3];
    int row = blockIdx.x;
    int b = row / NPTS;
    int tid = threadIdx.x;
    const float* bp = bxyz + (size_t)b*NPTS*3;
    for (int i = tid; i < NPTS*3; i += 256) sp[i] = bp[i];
    float qx = xyz[(size_t)row*3+0], qy = xyz[(size_t)row*3+1], qz = xyz[(size_t)row*3+2];
    float qn = qx*qx + qy*qy + qz*qz;
    __syncthreads();
    ull k64[8];
    #pragma unroll
    for (int i = 0; i < 8; i++){
        int m = tid + i*256;
        float px = sp[m*3+0], py = sp[m*3+1], pz = sp[m*3+2];
        float pn = px*px + py*py + pz*pz;
        float d = qn + pn - 2.f*(qx*px + qy*py + qz*pz);
        k64[i] = ((ull)fkey(d) << 16) | (ull)m;
    }
    select32_reg(k64, g_idx0 + (size_t)row*K_NN);
}

// ---------------- feature KNN selection ----------------
__global__ void select_feat_k(){
    int row = blockIdx.x;
    int tid = threadIdx.x;
    const float4* dr = (const float4*)(g_dist + (size_t)row*NPTS);
    ull k64[8];
    #pragma unroll
    for (int i = 0; i < 2; i++){
        float4 d4 = dr[i*256 + tid];
        int m = (i*256 + tid)*4;
        k64[i*4+0] = ((ull)fkey(d4.x) << 16) | (ull)(m+0);
        k64[i*4+1] = ((ull)fkey(d4.y) << 16) | (ull)(m+1);
        k64[i*4+2] = ((ull)fkey(d4.z) << 16) | (ull)(m+2);
        k64[i*4+3] = ((ull)fkey(d4.w) << 16) | (ull)(m+3);
    }
    select32_reg(k64, g_idx1 + (size_t)row*K_NN);
}

// ---------------- feature pairwise distance GEMM (fp32 SIMT — REQUIRED precision) ------
// 128x128 tile, 8x8 accum, conflict-free B mapping (tx + 16*j). R13-validated.
__global__ void __launch_bounds__(256) dist_gemm_k(const float* __restrict__ feat){
    int bz = blockIdx.z;
    const float* A = feat + (size_t)bz*NPTS*CIN;
    __shared__ float As[16][136];
    __shared__ float Bs[16][136];
    int tid = threadIdx.x, tx = tid & 15, ty = tid >> 4;
    int row0 = blockIdx.y*128, col0 = blockIdx.x*128;
    float acc[8][8] = {};
    int ar = tid >> 1, ac = (tid & 1) * 8;
    for (int k0 = 0; k0 < CIN; k0 += 16){
        float4 a4 = *(const float4*)(A + (size_t)(row0+ar)*CIN + k0 + ac);
        float4 a5 = *(const float4*)(A + (size_t)(row0+ar)*CIN + k0 + ac + 4);
        As[ac+0][ar]=a4.x; As[ac+1][ar]=a4.y; As[ac+2][ar]=a4.z; As[ac+3][ar]=a4.w;
        As[ac+4][ar]=a5.x; As[ac+5][ar]=a5.y; As[ac+6][ar]=a5.z; As[ac+7][ar]=a5.w;
        float4 b4 = *(const float4*)(A + (size_t)(col0+ar)*CIN + k0 + ac);
        float4 b5 = *(const float4*)(A + (size_t)(col0+ar)*CIN + k0 + ac + 4);
        Bs[ac+0][ar]=b4.x; Bs[ac+1][ar]=b4.y; Bs[ac+2][ar]=b4.z; Bs[ac+3][ar]=b4.w;
        Bs[ac+4][ar]=b5.x; Bs[ac+5][ar]=b5.y; Bs[ac+6][ar]=b5.z; Bs[ac+7][ar]=b5.w;
        __syncthreads();
        #pragma unroll
        for (int kk = 0; kk < 16; kk++){
            float av[8], bv[8];
            #pragma unroll
            for (int i=0;i<8;i++) av[i] = As[kk][ty*8+i];
            #pragma unroll
            for (int j=0;j<8;j++) bv[j] = Bs[kk][tx + 16*j];
            #pragma unroll
            for (int i=0;i<8;i++)
                #pragma unroll
                for (int j=0;j<8;j++) acc[i][j] += av[i]*bv[j];
        }
        __syncthreads();
    }
    float* D = g_dist + (size_t)bz*NPTS*NPTS;
    const float* qn = g_norms + bz*NPTS;
    #pragma unroll
    for (int i=0;i<8;i++){
        int n = row0 + ty*8 + i;
        float qnn = qn[n];
        #pragma unroll
        for (int j=0;j<8;j++){
            int m = col0 + tx + 16*j;
            D[(size_t)n*NPTS + m] = qnn + qn[m] - 2.f*acc[i][j];
        }
    }
}

// ================= 3xTF32 tensor-core GEMM (validated R7) =================
#define BM 128
#define BN 64
#define BKT 32
#define SM_WORDS (128*36*2 + 32*72*2)

struct GemmB { const float* A; const float* W; const float* bias; float* C; };
struct GemmP { GemmB b[8]; int K; };

__device__ __forceinline__ void mma_tf32(float* d, const uint32_t* a, const uint32_t* b){
    asm volatile(
        "mma.sync.aligned.m16n8k8.row.col.f32.tf32.tf32.f32 "
        "{%0,%1,%2,%3}, {%4,%5,%6,%7}, {%8,%9}, {%0,%1,%2,%3};\n"
        : "+f"(d[0]), "+f"(d[1]), "+f"(d[2]), "+f"(d[3])
        : "r"(a[0]), "r"(a[1]), "r"(a[2]), "r"(a[3]), "r"(b[0]), "r"(b[1]));
}

__global__ void __launch_bounds__(256) gemm3_k(GemmP p){
    __shared__ uint32_t sm[SM_WORDS];
    uint32_t (*Ah)[36] = (uint32_t(*)[36])sm;
    uint32_t (*Al)[36] = (uint32_t(*)[36])(sm + 128*36);
    uint32_t (*Bh)[72] = (uint32_t(*)[72])(sm + 128*36*2);
    uint32_t (*Bl)[72] = (uint32_t(*)[72])(sm + 128*36*2 + 32*72);

    int z = blockIdx.z;
    const float* A = p.b[z].A;
    const float* W = p.b[z].W;
    const float* bias = p.b[z].bias;
    float* C = p.b[z].C;
    int K = p.K;

    int tid = threadIdx.x, lane = tid & 31, wid = tid >> 5;
    int wm = (wid & 3) * 32, wn = (wid >> 2) * 32;
    int row0 = blockIdx.y*BM, col0 = blockIdx.x*BN;
    int g = lane >> 2, t = lane & 3;

    float acc[8][4];
    #pragma unroll
    for (int i=0;i<8;i++){ acc[i][0]=0.f; acc[i][1]=0.f; acc[i][2]=0.f; acc[i][3]=0.f; }

    int ar = tid >> 1, ac = (tid & 1) * 16;
    int br = tid >> 3, bc = (tid & 7) * 8;

    for (int k0 = 0; k0 < K; k0 += BKT){
        #pragma unroll
        for (int i = 0; i < 4; i++){
            float4 a4 = *(const float4*)(A + (size_t)(row0+ar)*K + k0 + ac + i*4);
            uint4 h4, l4;
            tf32_split(a4.x, h4.x, l4.x); tf32_split(a4.y, h4.y, l4.y);
            tf32_split(a4.z, h4.z, l4.z); tf32_split(a4.w, h4.w, l4.w);
            *(uint4*)&Ah[ar][ac+i*4] = h4;
            *(uint4*)&Al[ar][ac+i*4] = l4;
        }
        #pragma unroll
        for (int i = 0; i < 2; i++){
            float4 b4 = *(const float4*)(W + (size_t)(k0+br)*COUT + col0 + bc + i*4);
            uint4 h4, l4;
            tf32_split(b4.x, h4.x, l4.x); tf32_split(b4.y, h4.y, l4.y);
            tf32_split(b4.z, h4.z, l4.z); tf32_split(b4.w, h4.w, l4.w);
            *(uint4*)&Bh[br][bc+i*4] = h4;
            *(uint4*)&Bl[br][bc+i*4] = l4;
        }
        __syncthreads();
        #pragma unroll
        for (int ks = 0; ks < 4; ks++){
            int kb = ks*8;
            uint32_t ah[2][4], al[2][4], bh[4][2], bl[4][2];
            #pragma unroll
            for (int mi = 0; mi < 2; mi++){
                ah[mi][0] = Ah[wm+mi*16+g  ][kb+t  ]; al[mi][0] = Al[wm+mi*16+g  ][kb+t  ];
                ah[mi][1] = Ah[wm+mi*16+g+8][kb+t  ]; al[mi][1] = Al[wm+mi*16+g+8][kb+t  ];
                ah[mi][2] = Ah[wm+mi*16+g  ][kb+t+4]; al[mi][2] = Al[wm+mi*16+g  ][kb+t+4];
                ah[mi][3] = Ah[wm+mi*16+g+8][kb+t+4]; al[mi][3] = Al[wm+mi*16+g+8][kb+t+4];
            }
            #pragma unroll
            for (int ni = 0; ni < 4; ni++){
                bh[ni][0] = Bh[kb+t  ][wn+ni*8+g]; bl[ni][0] = Bl[kb+t  ][wn+ni*8+g];
                bh[ni][1] = Bh[kb+t+4][wn+ni*8+g]; bl[ni][1] = Bl[kb+t+4][wn+ni*8+g];
            }
            #pragma unroll
            for (int mi = 0; mi < 2; mi++)
                #pragma unroll
                for (int ni = 0; ni < 4; ni++){
                    float* d = acc[mi*4+ni];
                    mma_tf32(d, al[mi], bh[ni]);
                    mma_tf32(d, ah[mi], bl[ni]);
                    mma_tf32(d, ah[mi], bh[ni]);
                }
        }
        __syncthreads();
    }

    #pragma unroll
    for (int mi = 0; mi < 2; mi++){
        #pragma unroll
        for (int ni = 0; ni < 4; ni++){
            int col = col0 + wn + ni*8 + t*2;
            float b0 = bias[col], b1 = bias[col+1];
            float* d = acc[mi*4+ni];
            int r0 = row0 + wm + mi*16 + g;
            *(float2*)(C + (size_t)r0*COUT + col)     = make_float2(d[0]+b0, d[1]+b1);
            *(float2*)(C + (size_t)(r0+8)*COUT + col) = make_float2(d[2]+b0, d[3]+b1);
        }
    }
}

// ---------------- attention (single branch; fast exp) ----------------
__global__ void attn_k(const float* __restrict__ q_, const float* __restrict__ k_,
                       const float* __restrict__ v_, const int* __restrict__ idx_,
                       float* __restrict__ ctx_){
    int row = blockIdx.x;
    int bb = row / NPTS;
    __shared__ int gix[K_NN];
    if (threadIdx.x < K_NN) gix[threadIdx.x] = bb*NPTS + idx_[(size_t)row*K_NN + threadIdx.x];
    __syncthreads();
    int c = threadIdx.x;
    float q = q_[(size_t)row*COUT + c];
    float e[K_NN];
    float mx = -FINF;
    #pragma unroll
    for (int j = 0; j < K_NN; j++){
        float kk = k_[(size_t)gix[j]*COUT + c];
        float ee = (q - kk) * 0.0625f;
        e[j] = ee;
        mx = fmaxf(mx, ee);
    }
    float s = 0.f;
    #pragma unroll
    for (int j = 0; j < K_NN; j++){ e[j] = __expf(e[j] - mx); s += e[j]; }
    float inv = 1.f / s;
    float best = -FINF;
    #pragma unroll
    for (int j = 0; j < K_NN; j++){
        float att = e[j]*inv - 1.f;
        float vv = v_[(size_t)gix[j]*COUT + c];
        best = fmaxf(best, att*vv);
    }
    ctx_[(size_t)row*COUT + c] = best;
}

// ---------------- BatchNorm stats: deterministic two-stage ----------------
struct StatB { const float* x; int slot; };
struct StatP { StatB b[4]; };

__global__ void bn_stats_k(StatP p){
    StatB sb = p.b[blockIdx.z];
    int c = threadIdx.x;
    int r0 = blockIdx.x * (ROWS/64);
    float s = 0.f, sq = 0.f;
    for (int r = r0; r < r0 + ROWS/64; r++){
        float v = sb.x[(size_t)r*COUT + c];
        s += v; sq += v*v;
    }
    float* pp = g_part + (size_t)(sb.slot*64 + blockIdx.x)*2*COUT;
    pp[c] = s; pp[COUT + c] = sq;
}

struct FinB { const float* gamma; const float* beta; int slot; };
struct FinP { FinB b[4]; };

__global__ void bn_final_k(FinP p){
    FinB f = p.b[blockIdx.x];
    int c = threadIdx.x;
    float s = 0.f, sq = 0.f;
    for (int i = 0; i < 64; i++){
        const float* pp = g_part + (size_t)(f.slot*64 + i)*2*COUT;
        s += pp[c]; sq += pp[COUT + c];
    }
    float mean = s * (1.f/ROWS);
    float var  = sq * (1.f/ROWS) - mean*mean;
    float rstd = rsqrtf(var + 1e-5f);
    float aa = f.gamma[c] * rstd;
    g_coef[(f.slot*COUT + c)*2 + 0] = aa;
    g_coef[(f.slot*COUT + c)*2 + 1] = f.beta[c] - mean*aa;
}

// ---------------- combine residual + ffn per branch ----------------
__global__ void combine_k(){
    int row = blockIdx.x, c = threadIdx.x;
    const size_t RC = (size_t)ROWS*COUT;
    float x  = g_proj[3*RC + (size_t)row*COUT + c];
    float t  = g_coef[(0*COUT+c)*2]*x + g_coef[(0*COUT+c)*2+1];
    float r0 = lrelu(t);
    x = g_ffnh[(size_t)row*COUT + c];
    t = g_coef[(2*COUT+c)*2]*x + g_coef[(2*COUT+c)*2+1];
    float f0 = lrelu(t);
    g_mcat[(size_t)row*2*COUT + c] = r0 + f0;
    x = g_proj[7*RC + (size_t)row*COUT + c];
    t = g_coef[(1*COUT+c)*2]*x + g_coef[(1*COUT+c)*2+1];
    float r1 = lrelu(t);
    x = g_ffnh[RC + (size_t)row*COUT + c];
    t = g_coef[(3*COUT+c)*2]*x + g_coef[(3*COUT+c)*2+1];
    float f1 = lrelu(t);
    g_mcat[(size_t)row*2*COUT + COUT + c] = r1 + f1;
}

// ---------------- final BN + leaky relu ----------------
__global__ void final_k(float* __restrict__ out){
    int row = blockIdx.x, c = threadIdx.x;
    float x = g_mergeh[(size_t)row*COUT + c];
    float t = g_coef[(4*COUT+c)*2]*x + g_coef[(4*COUT+c)*2+1];
    out[(size_t)row*COUT + c] = lrelu(t);
}

// ---------------- host ----------------
extern "C" void kernel_launch(void* const* d_in, const int* in_sizes, int n_in,
                              void* d_out, int out_size){
    const float* xyz    = (const float*)d_in[0];
    const float* bxyz   = (const float*)d_in[1];
    const float* feat   = (const float*)d_in[2];
    const float* qW     = (const float*)d_in[3];
    const float* qb     = (const float*)d_in[4];
    const float* kW     = (const float*)d_in[5];
    const float* kb     = (const float*)d_in[6];
    const float* vW     = (const float*)d_in[7];
    const float* vb     = (const float*)d_in[8];
    const float* rW     = (const float*)d_in[9];
    const float* rb     = (const float*)d_in[10];
    const float* rg     = (const float*)d_in[11];
    const float* rbeta  = (const float*)d_in[12];
    const float* fW     = (const float*)d_in[13];
    const float* fb     = (const float*)d_in[14];
    const float* fg     = (const float*)d_in[15];
    const float* fbeta  = (const float*)d_in[16];
    const float* fcW    = (const float*)d_in[17];
    const float* fcb    = (const float*)d_in[18];
    const float* fcg    = (const float*)d_in[19];
    const float* fcbeta = (const float*)d_in[20];

    float *proj, *ctx, *ffnh, *mcat, *mergeh;
    int *idx0, *idx1;
    cudaGetSymbolAddress((void**)&proj,   g_proj);
    cudaGetSymbolAddress((void**)&ctx,    g_ctx);
    cudaGetSymbolAddress((void**)&ffnh,   g_ffnh);
    cudaGetSymbolAddress((void**)&mcat,   g_mcat);
    cudaGetSymbolAddress((void**)&mergeh, g_mergeh);
    cudaGetSymbolAddress((void**)&idx0,   g_idx0);
    cudaGetSymbolAddress((void**)&idx1,   g_idx1);

    // streams/events created once (outside capture), reused identically each call.
    static cudaStream_t s1 = nullptr, s2 = nullptr;
    static cudaEvent_t ev_root, ev1, ev2;
    if (!s1){
        cudaStreamCreate(&s1);
        cudaStreamCreate(&s2);
        cudaEventCreateWithFlags(&ev_root, cudaEventDisableTiming);
        cudaEventCreateWithFlags(&ev1,     cudaEventDisableTiming);
        cudaEventCreateWithFlags(&ev2,     cudaEventDisableTiming);
    }

    const size_t RC = (size_t)ROWS*COUT;

    // fork
    cudaEventRecord(ev_root, 0);
    cudaStreamWaitEvent(s1, ev_root, 0);
    cudaStreamWaitEvent(s2, ev_root, 0);

    // s1: xyz KNN
    knn_xyz_k<<<ROWS, 256, 0, s1>>>(xyz, bxyz);
    cudaEventRecord(ev1, s1);

    // s2: proj GEMMs -> res stats -> (wait idx0) -> attn0 -> ffn0 -> ffn0 stats
    {
        GemmP p; p.K = CIN;
        const float* Ws[8] = {qW, kW, vW, rW,
                              qW + CIN*COUT, kW + CIN*COUT, vW + CIN*COUT, rW + CIN*COUT};
        const float* Bs[8] = {qb, kb, vb, rb, qb + COUT, kb + COUT, vb + COUT, rb + COUT};
        for (int i = 0; i < 8; i++){ p.b[i].A = feat; p.b[i].W = Ws[i]; p.b[i].bias = Bs[i]; p.b[i].C = proj + (size_t)i*RC; }
        gemm3_k<<<dim3(COUT/BN, ROWS/BM, 8), 256, 0, s2>>>(p);
    }
    {
        StatP s; s.b[0] = {proj + 3*RC, 0}; s.b[1] = {proj + 7*RC, 1};
        bn_stats_k<<<dim3(64,1,2), 256, 0, s2>>>(s);
    }
    cudaStreamWaitEvent(s2, ev1, 0);
    attn_k<<<ROWS, 256, 0, s2>>>(proj + 0*RC, proj + 1*RC, proj + 2*RC, idx0, ctx);
    {
        GemmP p; p.K = COUT;
        p.b[0] = {ctx, fW, fb, ffnh};
        gemm3_k<<<dim3(COUT/BN, ROWS/BM, 1), 256, 0, s2>>>(p);
    }
    {
        StatP s; s.b[0] = {ffnh, 2};
        bn_stats_k<<<dim3(64,1,1), 256, 0, s2>>>(s);
    }
    cudaEventRecord(ev2, s2);

    // main: norms -> dist -> select -> attn1 -> ffn1 -> stats3
    norms_k<<<ROWS/8, 256>>>(feat);
    dist_gemm_k<<<dim3(NPTS/128, NPTS/128, BATCH), 256>>>(feat);
    select_feat_k<<<ROWS, 256>>>();
    attn_k<<<ROWS, 256>>>(proj + 4*RC, proj + 5*RC, proj + 6*RC, idx1, ctx + RC);
    {
        GemmP p; p.K = COUT;
        p.b[0] = {ctx + RC, fW + COUT*COUT, fb + COUT, ffnh + RC};
        gemm3_k<<<dim3(COUT/BN, ROWS/BM, 1), 256>>>(p);
    }
    {
        StatP s; s.b[0] = {ffnh + RC, 3};
        bn_stats_k<<<dim3(64,1,1), 256>>>(s);
    }

    // join branch-0 chain
    cudaStreamWaitEvent(0, ev2, 0);

    {
        FinP f;
        f.b[0] = {rg,        rbeta,        0};
        f.b[1] = {rg + COUT, rbeta + COUT, 1};
        f.b[2] = {fg,        fbeta,        2};
        f.b[3] = {fg + COUT, fbeta + COUT, 3};
        bn_final_k<<<4, 256>>>(f);
    }

    combine_k<<<ROWS, 256>>>();

    {
        GemmP p; p.K = 2*COUT;
        p.b[0] = {mcat, fcW, fcb, mergeh};
        gemm3_k<<<dim3(COUT/BN, ROWS/BM, 1), 256>>>(p);
    }

    {
        StatP s; s.b[0] = {mergeh, 4};
        bn_stats_k<<<dim3(64,1,1), 256>>>(s);
        FinP f; f.b[0] = {fcg, fcbeta, 4};
        bn_final_k<<<1, 256>>>(f);
    }

    final_k<<<ROWS, 256>>>((float*)d_out);
}

// round 17
// speedup vs baseline: 1.2042x; 1.0035x over previous
#include <cuda_runtime.h>
#include <cstdint>
#include <cstddef>

#define BATCH 4
#define NPTS  2048
#define ROWS  (BATCH*NPTS)   // 8192
#define CIN   128
#define COUT  256
#define K_NN  32

#define FINF __int_as_float(0x7f800000)
typedef unsigned long long ull;

// ---------------- scratch ----------------
__device__ float g_norms[ROWS];
__device__ float g_dist[(size_t)BATCH*NPTS*NPTS];          // 64 MB
__device__ int   g_idx0[ROWS*K_NN];
__device__ int   g_idx1[ROWS*K_NN];
__device__ float g_proj[(size_t)8*ROWS*COUT];              // q0,k0,v0,r0,q1,k1,v1,r1
__device__ float g_ctx[(size_t)2*ROWS*COUT];
__device__ float g_ffnh[(size_t)2*ROWS*COUT];
__device__ float g_mcat[(size_t)ROWS*2*COUT];
__device__ float g_mergeh[(size_t)ROWS*COUT];
__device__ float g_part[5*64*2*COUT];
__device__ float g_coef[5*COUT*2];

__device__ __forceinline__ float lrelu(float x){ return x > 0.f ? x : 0.2f*x; }

__device__ __forceinline__ uint32_t fkey(float f){
    uint32_t b = __float_as_uint(f);
    return b ^ (uint32_t)(((int)b >> 31) | 0x80000000);
}

// mask-based tf32 split (validated R7): hi = tf32 truncation, lo = exact residual.
__device__ __forceinline__ void tf32_split(float x, uint32_t& hi, uint32_t& lo){
    hi = __float_as_uint(x) & 0xFFFFE000u;
    lo = __float_as_uint(x - __uint_as_float(hi));
}

// ---------------- row squared norms of feature (one warp per row) ----------------
__global__ void norms_k(const float* __restrict__ feat){
    int w = (blockIdx.x*blockDim.x + threadIdx.x) >> 5;
    int lane = threadIdx.x & 31;
    if (w >= ROWS) return;
    float4 f4 = ((const float4*)(feat + (size_t)w*CIN))[lane];
    float s = f4.x*f4.x + f4.y*f4.y + f4.z*f4.z + f4.w*f4.w;
    #pragma unroll
    for (int o=16;o;o>>=1) s += __shfl_xor_sync(0xffffffffu, s, o);
    if (!lane) g_norms[w] = s;
}

// ---------------- register-key radix select (validated R10) ----------------
__device__ void select32_reg(const ull* __restrict__ k64, int* __restrict__ out){
    __shared__ int h[256];
    __shared__ int sc[256];
    __shared__ ull s_prefix, s_bound;
    __shared__ int s_need, s_done, s_cnt;
    int tid = threadIdx.x;
    if (tid == 0){ s_prefix = 0; s_need = K_NN; s_done = 0; s_cnt = 0; }
    int shift = 40;
    __syncthreads();
    while (true){
        h[tid] = 0;
        __syncthreads();
        ull pref = s_prefix;
        int need = s_need;
        #pragma unroll
        for (int i = 0; i < 8; i++){
            if ((k64[i] >> (shift + 8)) == pref)
                atomicAdd(&h[(int)((k64[i] >> shift) & 0xFF)], 1);
        }
        __syncthreads();
        int hv = h[tid];
        sc[tid] = hv;
        __syncthreads();
        #pragma unroll
        for (int o = 1; o < 256; o <<= 1){
            int u = (tid >= o) ? sc[tid - o] : 0;
            __syncthreads();
            sc[tid] += u;
            __syncthreads();
        }
        int incl = sc[tid], excl = incl - hv;
        if (excl < need && incl >= need){
            int nn = need - excl;
            if (hv == nn){
                s_bound = ((((pref << 8) | (ull)tid) + 1ull) << shift);
                s_done = 1;
            } else {
                s_prefix = (pref << 8) | (ull)tid;
                s_need = nn;
            }
        }
        __syncthreads();
        if (s_done) break;
        shift -= 8;
    }
    ull bound = s_bound;
    #pragma unroll
    for (int i = 0; i < 8; i++){
        if (k64[i] < bound){
            int p = atomicAdd(&s_cnt, 1);
            out[p] = (int)(k64[i] & 0xFFFFull);
        }
    }
}

// ---------------- xyz KNN: fused distance + reg-key selection ----------------
__global__ void knn_xyz_k(const float* __restrict__ xyz, const float* __restrict__ bxyz){
    __shared__ float sp[NPTS*3];
    int row = blockIdx.x;
    int b = row / NPTS;
    int tid = threadIdx.x;
    const float* bp = bxyz + (size_t)b*NPTS*3;
    for (int i = tid; i < NPTS*3; i += 256) sp[i] = bp[i];
    float qx = xyz[(size_t)row*3+0], qy = xyz[(size_t)row*3+1], qz = xyz[(size_t)row*3+2];
    float qn = qx*qx + qy*qy + qz*qz;
    __syncthreads();
    ull k64[8];
    #pragma unroll
    for (int i = 0; i < 8; i++){
        int m = tid + i*256;
        float px = sp[m*3+0], py = sp[m*3+1], pz = sp[m*3+2];
        float pn = px*px + py*py + pz*pz;
        float d = qn + pn - 2.f*(qx*px + qy*py + qz*pz);
        k64[i] = ((ull)fkey(d) << 16) | (ull)m;
    }
    select32_reg(k64, g_idx0 + (size_t)row*K_NN);
}

// ---------------- feature KNN selection ----------------
__global__ void select_feat_k(){
    int row = blockIdx.x;
    int tid = threadIdx.x;
    const float4* dr = (const float4*)(g_dist + (size_t)row*NPTS);
    ull k64[8];
    #pragma unroll
    for (int i = 0; i < 2; i++){
        float4 d4 = dr[i*256 + tid];
        int m = (i*256 + tid)*4;
        k64[i*4+0] = ((ull)fkey(d4.x) << 16) | (ull)(m+0);
        k64[i*4+1] = ((ull)fkey(d4.y) << 16) | (ull)(m+1);
        k64[i*4+2] = ((ull)fkey(d4.z) << 16) | (ull)(m+2);
        k64[i*4+3] = ((ull)fkey(d4.w) << 16) | (ull)(m+3);
    }
    select32_reg(k64, g_idx1 + (size_t)row*K_NN);
}

// ---------------- feature pairwise distance GEMM (fp32 SIMT — REQUIRED precision) ------
// 128x128 tile, 8x8 accum, conflict-free B mapping (tx + 16*j). R13-validated.
__global__ void __launch_bounds__(256) dist_gemm_k(const float* __restrict__ feat){
    int bz = blockIdx.z;
    const float* A = feat + (size_t)bz*NPTS*CIN;
    __shared__ float As[16][136];
    __shared__ float Bs[16][136];
    int tid = threadIdx.x, tx = tid & 15, ty = tid >> 4;
    int row0 = blockIdx.y*128, col0 = blockIdx.x*128;
    float acc[8][8] = {};
    int ar = tid >> 1, ac = (tid & 1) * 8;
    for (int k0 = 0; k0 < CIN; k0 += 16){
        float4 a4 = *(const float4*)(A + (size_t)(row0+ar)*CIN + k0 + ac);
        float4 a5 = *(const float4*)(A + (size_t)(row0+ar)*CIN + k0 + ac + 4);
        As[ac+0][ar]=a4.x; As[ac+1][ar]=a4.y; As[ac+2][ar]=a4.z; As[ac+3][ar]=a4.w;
        As[ac+4][ar]=a5.x; As[ac+5][ar]=a5.y; As[ac+6][ar]=a5.z; As[ac+7][ar]=a5.w;
        float4 b4 = *(const float4*)(A + (size_t)(col0+ar)*CIN + k0 + ac);
        float4 b5 = *(const float4*)(A + (size_t)(col0+ar)*CIN + k0 + ac + 4);
        Bs[ac+0][ar]=b4.x; Bs[ac+1][ar]=b4.y; Bs[ac+2][ar]=b4.z; Bs[ac+3][ar]=b4.w;
        Bs[ac+4][ar]=b5.x; Bs[ac+5][ar]=b5.y; Bs[ac+6][ar]=b5.z; Bs[ac+7][ar]=b5.w;
        __syncthreads();
        #pragma unroll
        for (int kk = 0; kk < 16; kk++){
            float av[8], bv[8];
            #pragma unroll
            for (int i=0;i<8;i++) av[i] = As[kk][ty*8+i];
            #pragma unroll
            for (int j=0;j<8;j++) bv[j] = Bs[kk][tx + 16*j];
            #pragma unroll
            for (int i=0;i<8;i++)
                #pragma unroll
                for (int j=0;j<8;j++) acc[i][j] += av[i]*bv[j];
        }
        __syncthreads();
    }
    float* D = g_dist + (size_t)bz*NPTS*NPTS;
    const float* qn = g_norms + bz*NPTS;
    #pragma unroll
    for (int i=0;i<8;i++){
        int n = row0 + ty*8 + i;
        float qnn = qn[n];
        #pragma unroll
        for (int j=0;j<8;j++){
            int m = col0 + tx + 16*j;
            D[(size_t)n*NPTS + m] = qnn + qn[m] - 2.f*acc[i][j];
        }
    }
}

// ================= 3xTF32 tensor-core GEMM (validated R7) =================
#define BM 128
#define BN 64
#define BKT 32
#define SM_WORDS (128*36*2 + 32*72*2)

struct GemmB { const float* A; const float* W; const float* bias; float* C; };
struct GemmP { GemmB b[8]; int K; };

__device__ __forceinline__ void mma_tf32(float* d, const uint32_t* a, const uint32_t* b){
    asm volatile(
        "mma.sync.aligned.m16n8k8.row.col.f32.tf32.tf32.f32 "
        "{%0,%1,%2,%3}, {%4,%5,%6,%7}, {%8,%9}, {%0,%1,%2,%3};\n"
        : "+f"(d[0]), "+f"(d[1]), "+f"(d[2]), "+f"(d[3])
        : "r"(a[0]), "r"(a[1]), "r"(a[2]), "r"(a[3]), "r"(b[0]), "r"(b[1]));
}

__global__ void __launch_bounds__(256) gemm3_k(GemmP p){
    __shared__ uint32_t sm[SM_WORDS];
    uint32_t (*Ah)[36] = (uint32_t(*)[36])sm;
    uint32_t (*Al)[36] = (uint32_t(*)[36])(sm + 128*36);
    uint32_t (*Bh)[72] = (uint32_t(*)[72])(sm + 128*36*2);
    uint32_t (*Bl)[72] = (uint32_t(*)[72])(sm + 128*36*2 + 32*72);

    int z = blockIdx.z;
    const float* A = p.b[z].A;
    const float* W = p.b[z].W;
    const float* bias = p.b[z].bias;
    float* C = p.b[z].C;
    int K = p.K;

    int tid = threadIdx.x, lane = tid & 31, wid = tid >> 5;
    int wm = (wid & 3) * 32, wn = (wid >> 2) * 32;
    int row0 = blockIdx.y*BM, col0 = blockIdx.x*BN;
    int g = lane >> 2, t = lane & 3;

    float acc[8][4];
    #pragma unroll
    for (int i=0;i<8;i++){ acc[i][0]=0.f; acc[i][1]=0.f; acc[i][2]=0.f; acc[i][3]=0.f; }

    int ar = tid >> 1, ac = (tid & 1) * 16;
    int br = tid >> 3, bc = (tid & 7) * 8;

    for (int k0 = 0; k0 < K; k0 += BKT){
        #pragma unroll
        for (int i = 0; i < 4; i++){
            float4 a4 = *(const float4*)(A + (size_t)(row0+ar)*K + k0 + ac + i*4);
            uint4 h4, l4;
            tf32_split(a4.x, h4.x, l4.x); tf32_split(a4.y, h4.y, l4.y);
            tf32_split(a4.z, h4.z, l4.z); tf32_split(a4.w, h4.w, l4.w);
            *(uint4*)&Ah[ar][ac+i*4] = h4;
            *(uint4*)&Al[ar][ac+i*4] = l4;
        }
        #pragma unroll
        for (int i = 0; i < 2; i++){
            float4 b4 = *(const float4*)(W + (size_t)(k0+br)*COUT + col0 + bc + i*4);
            uint4 h4, l4;
            tf32_split(b4.x, h4.x, l4.x); tf32_split(b4.y, h4.y, l4.y);
            tf32_split(b4.z, h4.z, l4.z); tf32_split(b4.w, h4.w, l4.w);
            *(uint4*)&Bh[br][bc+i*4] = h4;
            *(uint4*)&Bl[br][bc+i*4] = l4;
        }
        __syncthreads();
        #pragma unroll
        for (int ks = 0; ks < 4; ks++){
            int kb = ks*8;
            uint32_t ah[2][4], al[2][4], bh[4][2], bl[4][2];
            #pragma unroll
            for (int mi = 0; mi < 2; mi++){
                ah[mi][0] = Ah[wm+mi*16+g  ][kb+t  ]; al[mi][0] = Al[wm+mi*16+g  ][kb+t  ];
                ah[mi][1] = Ah[wm+mi*16+g+8][kb+t  ]; al[mi][1] = Al[wm+mi*16+g+8][kb+t  ];
                ah[mi][2] = Ah[wm+mi*16+g  ][kb+t+4]; al[mi][2] = Al[wm+mi*16+g  ][kb+t+4];
                ah[mi][3] = Ah[wm+mi*16+g+8][kb+t+4]; al[mi][3] = Al[wm+mi*16+g+8][kb+t+4];
            }
            #pragma unroll
            for (int ni = 0; ni < 4; ni++){
                bh[ni][0] = Bh[kb+t  ][wn+ni*8+g]; bl[ni][0] = Bl[kb+t  ][wn+ni*8+g];
                bh[ni][1] = Bh[kb+t+4][wn+ni*8+g]; bl[ni][1] = Bl[kb+t+4][wn+ni*8+g];
            }
            #pragma unroll
            for (int mi = 0; mi < 2; mi++)
                #pragma unroll
                for (int ni = 0; ni < 4; ni++){
                    float* d = acc[mi*4+ni];
                    mma_tf32(d, al[mi], bh[ni]);
                    mma_tf32(d, ah[mi], bl[ni]);
                    mma_tf32(d, ah[mi], bh[ni]);
                }
        }
        __syncthreads();
    }

    #pragma unroll
    for (int mi = 0; mi < 2; mi++){
        #pragma unroll
        for (int ni = 0; ni < 4; ni++){
            int col = col0 + wn + ni*8 + t*2;
            float b0 = bias[col], b1 = bias[col+1];
            float* d = acc[mi*4+ni];
            int r0 = row0 + wm + mi*16 + g;
            *(float2*)(C + (size_t)r0*COUT + col)     = make_float2(d[0]+b0, d[1]+b1);
            *(float2*)(C + (size_t)(r0+8)*COUT + col) = make_float2(d[2]+b0, d[3]+b1);
        }
    }
}

// ---------------- attention: 3-pass, no register array (bitwise == R16 chains) --------
__global__ void attn_k(const float* __restrict__ q_, const float* __restrict__ k_,
                       const float* __restrict__ v_, const int* __restrict__ idx_,
                       float* __restrict__ ctx_){
    int row = blockIdx.x;
    int bb = row / NPTS;
    __shared__ ull roff[K_NN];   // precomputed row offsets gix[j]*COUT
    if (threadIdx.x < K_NN){
        int g = bb*NPTS + idx_[(size_t)row*K_NN + threadIdx.x];
        roff[threadIdx.x] = (ull)g * COUT;
    }
    __syncthreads();
    int c = threadIdx.x;
    float q = q_[(size_t)row*COUT + c];

    // pass 1: max of ee
    float mx = -FINF;
    #pragma unroll
    for (int j = 0; j < K_NN; j++){
        float kk = k_[roff[j] + c];
        float ee = (q - kk) * 0.0625f;
        mx = fmaxf(mx, ee);
    }
    // pass 2: sum of exp(ee - mx), j-order
    float s = 0.f;
    #pragma unroll
    for (int j = 0; j < K_NN; j++){
        float kk = k_[roff[j] + c];
        float ee = (q - kk) * 0.0625f;
        s += __expf(ee - mx);
    }
    float inv = 1.f / s;
    // pass 3: maxpool of (exp*inv - 1) * v
    float best = -FINF;
    #pragma unroll
    for (int j = 0; j < K_NN; j++){
        float kk = k_[roff[j] + c];
        float ee = (q - kk) * 0.0625f;
        float att = __expf(ee - mx)*inv - 1.f;
        float vv = v_[roff[j] + c];
        best = fmaxf(best, att*vv);
    }
    ctx_[(size_t)row*COUT + c] = best;
}

// ---------------- BatchNorm stats: deterministic two-stage ----------------
struct StatB { const float* x; int slot; };
struct StatP { StatB b[4]; };

__global__ void bn_stats_k(StatP p){
    StatB sb = p.b[blockIdx.z];
    int c = threadIdx.x;
    int r0 = blockIdx.x * (ROWS/64);
    float s = 0.f, sq = 0.f;
    for (int r = r0; r < r0 + ROWS/64; r++){
        float v = sb.x[(size_t)r*COUT + c];
        s += v; sq += v*v;
    }
    float* pp = g_part + (size_t)(sb.slot*64 + blockIdx.x)*2*COUT;
    pp[c] = s; pp[COUT + c] = sq;
}

struct FinB { const float* gamma; const float* beta; int slot; };
struct FinP { FinB b[4]; };

__global__ void bn_final_k(FinP p){
    FinB f = p.b[blockIdx.x];
    int c = threadIdx.x;
    float s = 0.f, sq = 0.f;
    for (int i = 0; i < 64; i++){
        const float* pp = g_part + (size_t)(f.slot*64 + i)*2*COUT;
        s += pp[c]; sq += pp[COUT + c];
    }
    float mean = s * (1.f/ROWS);
    float var  = sq * (1.f/ROWS) - mean*mean;
    float rstd = rsqrtf(var + 1e-5f);
    float aa = f.gamma[c] * rstd;
    g_coef[(f.slot*COUT + c)*2 + 0] = aa;
    g_coef[(f.slot*COUT + c)*2 + 1] = f.beta[c] - mean*aa;
}

// ---------------- combine residual + ffn per branch ----------------
__global__ void combine_k(){
    int row = blockIdx.x, c = threadIdx.x;
    const size_t RC = (size_t)ROWS*COUT;
    float x  = g_proj[3*RC + (size_t)row*COUT + c];
    float t  = g_coef[(0*COUT+c)*2]*x + g_coef[(0*COUT+c)*2+1];
    float r0 = lrelu(t);
    x = g_ffnh[(size_t)row*COUT + c];
    t = g_coef[(2*COUT+c)*2]*x + g_coef[(2*COUT+c)*2+1];
    float f0 = lrelu(t);
    g_mcat[(size_t)row*2*COUT + c] = r0 + f0;
    x = g_proj[7*RC + (size_t)row*COUT + c];
    t = g_coef[(1*COUT+c)*2]*x + g_coef[(1*COUT+c)*2+1];
    float r1 = lrelu(t);
    x = g_ffnh[RC + (size_t)row*COUT + c];
    t = g_coef[(3*COUT+c)*2]*x + g_coef[(3*COUT+c)*2+1];
    float f1 = lrelu(t);
    g_mcat[(size_t)row*2*COUT + COUT + c] = r1 + f1;
}

// ---------------- final BN + leaky relu ----------------
__global__ void final_k(float* __restrict__ out){
    int row = blockIdx.x, c = threadIdx.x;
    float x = g_mergeh[(size_t)row*COUT + c];
    float t = g_coef[(4*COUT+c)*2]*x + g_coef[(4*COUT+c)*2+1];
    out[(size_t)row*COUT + c] = lrelu(t);
}

// ---------------- host ----------------
extern "C" void kernel_launch(void* const* d_in, const int* in_sizes, int n_in,
                              void* d_out, int out_size){
    const float* xyz    = (const float*)d_in[0];
    const float* bxyz   = (const float*)d_in[1];
    const float* feat   = (const float*)d_in[2];
    const float* qW     = (const float*)d_in[3];
    const float* qb     = (const float*)d_in[4];
    const float* kW     = (const float*)d_in[5];
    const float* kb     = (const float*)d_in[6];
    const float* vW     = (const float*)d_in[7];
    const float* vb     = (const float*)d_in[8];
    const float* rW     = (const float*)d_in[9];
    const float* rb     = (const float*)d_in[10];
    const float* rg     = (const float*)d_in[11];
    const float* rbeta  = (const float*)d_in[12];
    const float* fW     = (const float*)d_in[13];
    const float* fb     = (const float*)d_in[14];
    const float* fg     = (const float*)d_in[15];
    const float* fbeta  = (const float*)d_in[16];
    const float* fcW    = (const float*)d_in[17];
    const float* fcb    = (const float*)d_in[18];
    const float* fcg    = (const float*)d_in[19];
    const float* fcbeta = (const float*)d_in[20];

    float *proj, *ctx, *ffnh, *mcat, *mergeh;
    int *idx0, *idx1;
    cudaGetSymbolAddress((void**)&proj,   g_proj);
    cudaGetSymbolAddress((void**)&ctx,    g_ctx);
    cudaGetSymbolAddress((void**)&ffnh,   g_ffnh);
    cudaGetSymbolAddress((void**)&mcat,   g_mcat);
    cudaGetSymbolAddress((void**)&mergeh, g_mergeh);
    cudaGetSymbolAddress((void**)&idx0,   g_idx0);
    cudaGetSymbolAddress((void**)&idx1,   g_idx1);

    // streams/events created once (outside capture), reused identically each call.
    static cudaStream_t s1 = nullptr, s2 = nullptr;
    static cudaEvent_t ev_root, ev1, ev2;
    if (!s1){
        cudaStreamCreate(&s1);
        cudaStreamCreate(&s2);
        cudaEventCreateWithFlags(&ev_root, cudaEventDisableTiming);
        cudaEventCreateWithFlags(&ev1,     cudaEventDisableTiming);
        cudaEventCreateWithFlags(&ev2,     cudaEventDisableTiming);
    }

    const size_t RC = (size_t)ROWS*COUT;

    // fork
    cudaEventRecord(ev_root, 0);
    cudaStreamWaitEvent(s1, ev_root, 0);
    cudaStreamWaitEvent(s2, ev_root, 0);

    // s1: xyz KNN
    knn_xyz_k<<<ROWS, 256, 0, s1>>>(xyz, bxyz);
    cudaEventRecord(ev1, s1);

    // s2: proj GEMMs -> res stats -> (wait idx0) -> attn0 -> ffn0 -> ffn0 stats
    {
        GemmP p; p.K = CIN;
        const float* Ws[8] = {qW, kW, vW, rW,
                              qW + CIN*COUT, kW + CIN*COUT, vW + CIN*COUT, rW + CIN*COUT};
        const float* Bs[8] = {qb, kb, vb, rb, qb + COUT, kb + COUT, vb + COUT, rb + COUT};
        for (int i = 0; i < 8; i++){ p.b[i].A = feat; p.b[i].W = Ws[i]; p.b[i].bias = Bs[i]; p.b[i].C = proj + (size_t)i*RC; }
        gemm3_k<<<dim3(COUT/BN, ROWS/BM, 8), 256, 0, s2>>>(p);
    }
    {
        StatP s; s.b[0] = {proj + 3*RC, 0}; s.b[1] = {proj + 7*RC, 1};
        bn_stats_k<<<dim3(64,1,2), 256, 0, s2>>>(s);
    }
    cudaStreamWaitEvent(s2, ev1, 0);
    attn_k<<<ROWS, 256, 0, s2>>>(proj + 0*RC, proj + 1*RC, proj + 2*RC, idx0, ctx);
    {
        GemmP p; p.K = COUT;
        p.b[0] = {ctx, fW, fb, ffnh};
        gemm3_k<<<dim3(COUT/BN, ROWS/BM, 1), 256, 0, s2>>>(p);
    }
    {
        StatP s; s.b[0] = {ffnh, 2};
        bn_stats_k<<<dim3(64,1,1), 256, 0, s2>>>(s);
    }
    cudaEventRecord(ev2, s2);

    // main: norms -> dist -> select -> attn1 -> ffn1 -> stats3
    norms_k<<<ROWS/8, 256>>>(feat);
    dist_gemm_k<<<dim3(NPTS/128, NPTS/128, BATCH), 256>>>(feat);
    select_feat_k<<<ROWS, 256>>>();
    attn_k<<<ROWS, 256>>>(proj + 4*RC, proj + 5*RC, proj + 6*RC, idx1, ctx + RC);
    {
        GemmP p; p.K = COUT;
        p.b[0] = {ctx + RC, fW + COUT*COUT, fb + COUT, ffnh + RC};
        gemm3_k<<<dim3(COUT/BN, ROWS/BM, 1), 256>>>(p);
    }
    {
        StatP s; s.b[0] = {ffnh + RC, 3};
        bn_stats_k<<<dim3(64,1,1), 256>>>(s);
    }

    // join branch-0 chain
    cudaStreamWaitEvent(0, ev2, 0);

    {
        FinP f;
        f.b[0] = {rg,        rbeta,        0};
        f.b[1] = {rg + COUT, rbeta + COUT, 1};
        f.b[2] = {fg,        fbeta,        2};
        f.b[3] = {fg + COUT, fbeta + COUT, 3};
        bn_final_k<<<4, 256>>>(f);
    }

    combine_k<<<ROWS, 256>>>();

    {
        GemmP p; p.K = 2*COUT;
        p.b[0] = {mcat, fcW, fcb, mergeh};
        gemm3_k<<<dim3(COUT/BN, ROWS/BM, 1), 256>>>(p);
    }

    {
        StatP s; s.b[0] = {mergeh, 4};
        bn_stats_k<<<dim3(64,1,1), 256>>>(s);
        FinP f; f.b[0] = {fcg, fcbeta, 4};
        bn_final_k<<<1, 256>>>(f);
    }

    final_k<<<ROWS, 256>>>((float*)d_out);
}